// round 9
// baseline (speedup 1.0000x reference)
#include <cuda_runtime.h>
#include <cuda_bf16.h>
#include <stdint.h>
#include <math.h>

#define NB 8
#define LQ 4096

// ---------------- device scratch (zero-init BSS, no allocation) ----------------
__device__ float g_xz   [(long)NB*384*LQ];
__device__ float g_t    [(long)NB*384*LQ];
__device__ float g_t2   [(long)NB*384*LQ];
__device__ float g_zsil [(long)NB*192*LQ];
__device__ float g_xc   [(long)NB*192*LQ];
__device__ float g_yL   [(long)NB*8*LQ];
__device__ float g_ym   [(long)NB*8*LQ];
__device__ float g_xdbl [(long)NB*22*LQ];
__device__ float g_delta[(long)NB*192*LQ];
__device__ float g_BC   [(long)NB*LQ*16];
__device__ float g_y    [(long)NB*192*LQ];
__device__ float g_yn   [(long)NB*192*LQ];
__device__ float g_A    [192*8];
__device__ int   g_pow_ok;

// ---------------- prep ----------------
__global__ void prep_kernel(const float* __restrict__ Alogs)
{
    int t = blockIdx.x * 256 + threadIdx.x;
    if (t < 192*8) g_A[t] = -expf(Alogs[t]);
}

__global__ void prep2_kernel()
{
    __shared__ int ok;
    if (threadIdx.x == 0) ok = 1;
    __syncthreads();
    for (int d = threadIdx.x; d < 192; d += 256) {
        float a0 = g_A[d * 8];
        for (int n = 1; n < 8; n++) {
            float expect = a0 * (float)(n + 1);
            float got = g_A[d * 8 + n];
            if (fabsf(got - expect) > 1e-5f * fabsf(expect)) atomicAnd(&ok, 0);
        }
    }
    __syncthreads();
    if (threadIdx.x == 0) g_pow_ok = ok;
}

__device__ __forceinline__ float gelu_exact(float v)
{
    return 0.5f * v * (1.f + erff(v * 0.70710678118654752f));
}

// ---------------- tf32 tensor-core GEMM, paired-k smem layout (LDS.64 frags) ---------
// W smem:  idx = row*40 + (kk&3)*10 + (kk>>2)          (2560 words)
// Act smem: idx = (kk&3)*1288 + m*10 + (kk>>2)          (5152 words)
// -> fragment elements (k, k+4) are adjacent 8B-aligned pairs.
#define SW_WORDS 2560
#define SA_WORDS 5152

__device__ __forceinline__ uint32_t f2tf32(float f)
{
    uint32_t o;
    asm("cvt.rna.tf32.f32 %0, %1;" : "=r"(o) : "f"(f));
    return o;
}

__device__ __forceinline__ void mma_tf32(float* d, const uint32_t* a, const uint32_t* b)
{
    asm volatile("mma.sync.aligned.m16n8k8.row.col.f32.tf32.tf32.f32 "
                 "{%0,%1,%2,%3}, {%4,%5,%6,%7}, {%8,%9}, {%0,%1,%2,%3};"
                 : "+f"(d[0]), "+f"(d[1]), "+f"(d[2]), "+f"(d[3])
                 : "r"(a[0]), "r"(a[1]), "r"(a[2]), "r"(a[3]),
                   "r"(b[0]), "r"(b[1]));
}

__device__ __forceinline__ void epi_store(float* Ob, float* O2b, int n, int m, float v, int EPI)
{
    if (EPI == 1) {
        if (n < 96) O2b[(long)n * LQ + m] = gelu_exact(v);
        else        Ob [(long)n * LQ + m] = v;
    } else if (EPI == 2) {
        int tr = ((m & 63) << 6) | (m >> 6);
        Ob[(long)n * LQ + tr] = v / (1.f + __expf(-v));
    } else {
        Ob[(long)n * LQ + m] = v;
    }
}

template<bool SPLIT, int EPI>
__global__ void __launch_bounds__(256)
gemm_tf32_kernel(const float* __restrict__ Act, long actStride,
                 const float* __restrict__ W, const float* __restrict__ bias,
                 float* __restrict__ O, float* __restrict__ O2,
                 long oStride, int N, int K)
{
    extern __shared__ uint32_t dsm[];
    uint32_t* sWb = dsm;
    uint32_t* sWs = SPLIT ? (dsm + SW_WORDS) : dsm;
    uint32_t* sAb = dsm + (SPLIT ? 2 : 1) * SW_WORDS;
    uint32_t* sAs = SPLIT ? (sAb + SA_WORDS) : sAb;

    const float* Ab = Act + (long)blockIdx.z * actStride;
    float* Ob = O + (long)blockIdx.z * oStride;
    float* O2b = O2 ? (O2 + (long)blockIdx.z * oStride) : nullptr;
    int m0 = blockIdx.x * 128, n0 = blockIdx.y * 64;
    int tid = threadIdx.x, lane = tid & 31, wid = tid >> 5;
    int wn = (wid & 1) * 32;
    int wm = (wid >> 1) * 32;

    float d[2][4][4];
#pragma unroll
    for (int i = 0; i < 2; i++)
#pragma unroll
        for (int j = 0; j < 4; j++)
#pragma unroll
            for (int q = 0; q < 4; q++) d[i][j][q] = 0.f;

    for (int kc = 0; kc < K; kc += 32) {
        // W tile [64 n][32 k] -> paired-k layout
#pragma unroll
        for (int i = 0; i < 2; i++) {
            int e = tid + i * 256;
            int row = e >> 3, j = e & 7;
            int n = n0 + row;
            float4 v = make_float4(0.f, 0.f, 0.f, 0.f);
            if (n < N) v = *(const float4*)(W + (long)n * K + kc + j * 4);
            float vv[4] = {v.x, v.y, v.z, v.w};
#pragma unroll
            for (int t = 0; t < 4; t++) {
                int idx = row * 40 + t * 10 + j;   // kk = 4j+t -> (kk&3)=t, (kk>>2)=j
                uint32_t bg = f2tf32(vv[t]);
                sWb[idx] = bg;
                if constexpr (SPLIT)
                    sWs[idx] = f2tf32(vv[t] - __uint_as_float(bg));
            }
        }
        // Act tile [32 k][128 m] -> paired-k layout
#pragma unroll
        for (int i = 0; i < 4; i++) {
            int e = tid + i * 256;
            int kk = e >> 5, c4 = (e & 31) * 4;
            float4 v = *(const float4*)(Ab + (long)(kc + kk) * LQ + m0 + c4);
            float vv[4] = {v.x, v.y, v.z, v.w};
            int kb = (kk & 3) * 1288 + (kk >> 2);
#pragma unroll
            for (int t = 0; t < 4; t++) {
                int idx = kb + (c4 + t) * 10;
                uint32_t bg = f2tf32(vv[t]);
                sAb[idx] = bg;
                if constexpr (SPLIT)
                    sAs[idx] = f2tf32(vv[t] - __uint_as_float(bg));
            }
        }
        __syncthreads();

#pragma unroll
        for (int ks = 0; ks < 4; ks++) {
            uint32_t afrB[2][4], bfrB[4][2];
            uint32_t afrS[2][4], bfrS[4][2];
            int acg = (lane & 3) * 10 + 2 * ks;
            int r = wn + (lane >> 2);
#pragma unroll
            for (int i = 0; i < 2; i++) {
                int rb = r + i * 16;
                uint2 a0 = *(const uint2*)&sWb[rb * 40 + acg];
                uint2 a1 = *(const uint2*)&sWb[(rb + 8) * 40 + acg];
                afrB[i][0] = a0.x; afrB[i][2] = a0.y;
                afrB[i][1] = a1.x; afrB[i][3] = a1.y;
                if constexpr (SPLIT) {
                    uint2 s0 = *(const uint2*)&sWs[rb * 40 + acg];
                    uint2 s1 = *(const uint2*)&sWs[(rb + 8) * 40 + acg];
                    afrS[i][0] = s0.x; afrS[i][2] = s0.y;
                    afrS[i][1] = s1.x; afrS[i][3] = s1.y;
                }
            }
            int bcg = (lane & 3) * 1288 + 2 * ks;
            int mcol = wm + (lane >> 2);
#pragma unroll
            for (int j = 0; j < 4; j++) {
                uint2 bv = *(const uint2*)&sAb[bcg + (mcol + j * 8) * 10];
                bfrB[j][0] = bv.x; bfrB[j][1] = bv.y;
                if constexpr (SPLIT) {
                    uint2 sv = *(const uint2*)&sAs[bcg + (mcol + j * 8) * 10];
                    bfrS[j][0] = sv.x; bfrS[j][1] = sv.y;
                }
            }
#pragma unroll
            for (int i = 0; i < 2; i++)
#pragma unroll
                for (int j = 0; j < 4; j++) {
                    if constexpr (SPLIT) {
                        mma_tf32(d[i][j], afrB[i], bfrS[j]);
                        mma_tf32(d[i][j], afrS[i], bfrB[j]);
                    }
                    mma_tf32(d[i][j], afrB[i], bfrB[j]);
                }
        }
        __syncthreads();
    }

#pragma unroll
    for (int i = 0; i < 2; i++) {
        int n = n0 + wn + i * 16 + (lane >> 2);
        float bb0 = (bias && n < N) ? bias[n] : 0.f;
        float bb1 = (bias && n + 8 < N) ? bias[n + 8] : 0.f;
#pragma unroll
        for (int j = 0; j < 4; j++) {
            int m = m0 + wm + j * 8 + 2 * (lane & 3);
            if (n < N) {
                epi_store(Ob, O2b, n, m,     d[i][j][0] + bb0, EPI);
                epi_store(Ob, O2b, n, m + 1, d[i][j][1] + bb0, EPI);
            }
            if (n + 8 < N) {
                epi_store(Ob, O2b, n + 8, m,     d[i][j][2] + bb1, EPI);
                epi_store(Ob, O2b, n + 8, m + 1, d[i][j][3] + bb1, EPI);
            }
        }
    }
}

// ---------------- z branch: merged multi-scale depthwise conv + GELU ----------------
template<int KSZ>
__device__ __forceinline__ void dwconv_body(float* sm, const float* __restrict__ W,
                                            const float* __restrict__ bias,
                                            int c, int b, int co)
{
    constexpr int PAD = KSZ / 2;
    constexpr int SH = 64 + 2 * PAD;
    int tid = threadIdx.x;
    const float* src = g_t + ((long)b * 384 + co) * LQ;

    for (int e = tid; e < SH * 72; e += 256) sm[e] = 0.f;
    __syncthreads();
    for (int e = tid; e < LQ; e += 256) {
        int h = e >> 6, w = e & 63;
        sm[(h + PAD) * 72 + (w + PAD)] = src[e];
    }
    __syncthreads();

    float wreg[KSZ * KSZ];
#pragma unroll
    for (int i = 0; i < KSZ * KSZ; i++) wreg[i] = W[c * KSZ * KSZ + i];
    float bb = bias[c];

    float* dst = g_t2 + ((long)b * 384 + co) * LQ;
    for (int e = tid; e < LQ; e += 256) {
        int h = e >> 6, w = e & 63;
        float acc = bb;
#pragma unroll
        for (int ky = 0; ky < KSZ; ky++) {
            const float* row = sm + (h + ky) * 72 + w;
#pragma unroll
            for (int kx = 0; kx < KSZ; kx++)
                acc += row[kx] * wreg[ky * KSZ + kx];
        }
        dst[e] = gelu_exact(acc);
    }
}

__global__ void dwconv_all_kernel(const float* __restrict__ W3, const float* __restrict__ b3,
                                  const float* __restrict__ W5, const float* __restrict__ b5,
                                  const float* __restrict__ W7, const float* __restrict__ b7)
{
    __shared__ float sm[70 * 72];   // sized for KSZ=7
    int cc = blockIdx.x;            // 0..287
    int b = blockIdx.y;
    if (cc < 96)       dwconv_body<3>(sm, W3, b3, cc,        b,  96 + cc);
    else if (cc < 192) dwconv_body<5>(sm, W5, b5, cc - 96,   b, 192 + (cc - 96));
    else               dwconv_body<7>(sm, W7, b7, cc - 192,  b, 288 + (cc - 192));
}

// ---------------- x branch: depthwise 3x3 + bias + silu ----------------
__global__ void dw3_silu_kernel(const float* __restrict__ W, const float* __restrict__ bias)
{
    __shared__ float sm[66 * 68];
    int c = blockIdx.x;
    int b = blockIdx.y;
    int tid = threadIdx.x;
    const float* src = g_xz + ((long)b * 384 + c) * LQ;
    for (int e = tid; e < 66 * 68; e += 256) sm[e] = 0.f;
    __syncthreads();
    for (int e = tid; e < LQ; e += 256) {
        int h = e >> 6, w = e & 63;
        sm[(h + 1) * 68 + (w + 1)] = src[e];
    }
    __syncthreads();
    float w0 = W[c*9+0], w1 = W[c*9+1], w2 = W[c*9+2];
    float w3 = W[c*9+3], w4 = W[c*9+4], w5 = W[c*9+5];
    float w6 = W[c*9+6], w7 = W[c*9+7], w8 = W[c*9+8];
    float bb = bias[c];
    float* dst = g_xc + ((long)b * 192 + c) * LQ;
    for (int e = tid; e < LQ; e += 256) {
        int h = e >> 6, w = e & 63;
        const float* r0 = sm + h * 68 + w;
        float acc = bb + r0[0]*w0 + r0[1]*w1 + r0[2]*w2
                       + r0[68]*w3 + r0[69]*w4 + r0[70]*w5
                       + r0[136]*w6 + r0[137]*w7 + r0[138]*w8;
        dst[e] = acc / (1.f + __expf(-acc));
    }
}

// ---------------- haar 1x1 conv + strided combine -> yL, y_mean ----------------
__global__ void haar_kernel(const float* __restrict__ Wh)
{
    extern __shared__ float smh[];
    float* sW = smh;
    float* s1 = smh + 32 * 192;
    float* s2 = s1 + 192 * 32;
    int i = blockIdx.x, b = blockIdx.y;
    int tid = threadIdx.x;
    for (int e = tid; e < 32 * 192; e += 256) sW[e] = Wh[e];
    const float* xcb = g_xc + (long)b * 192 * LQ;
    for (int e = tid; e < 192 * 32; e += 256) {
        int d = e >> 5, j = e & 31;
        const float* row0 = xcb + (long)d * LQ + (2 * i) * 64 + 2 * j;
        float xa = row0[0], xb = row0[1];
        float xc2 = row0[64], xd = row0[65];
        s1[d * 32 + j] = xa + xb + xc2 + xd;
        s2[d * 32 + j] = 3.f * xa - xb - xc2 - xd;
    }
    __syncthreads();
    for (int e = tid; e < 2048; e += 256) {
        int which = e >> 10;
        int ch = (e >> 5) & 31;
        int j = e & 31;
        const float* sv = (which ? s2 : s1) + j;
        const float* wr = sW + ch * 192;
        float acc = 0.f;
#pragma unroll 4
        for (int d = 0; d < 192; d++) acc += wr[d] * sv[d * 32];
        acc *= which ? (1.f / 6.f) : 0.5f;
        int n = ch >> 2;
        int lpos = (ch & 3) * 1024 + i * 32 + j;
        float* dst = which ? g_ym : g_yL;
        dst[((long)b * 8 + n) * LQ + lpos] = acc;
    }
}

// ---------------- fused: conv1d(k=7) + dt projection + softplus + B/C assembly --------
__global__ void convdtbc_kernel(const float* __restrict__ Wx, const float* __restrict__ bx,
                                const float* __restrict__ Wdt, const float* __restrict__ dtb)
{
    __shared__ float sIn[22][264];
    __shared__ float sWd[192 * 6];
    __shared__ float sBd[192];
    __shared__ float sWc[22 * 7];
    __shared__ float sbc[22];
    int tid = threadIdx.x;
    int l0 = blockIdx.x * 256;
    int b = blockIdx.y;

    for (int e = tid; e < 1152; e += 256) sWd[e] = Wdt[e];
    for (int e = tid; e < 192; e += 256) sBd[e] = dtb[e];
    for (int e = tid; e < 154; e += 256) sWc[e] = Wx[e];
    for (int e = tid; e < 22; e += 256) sbc[e] = bx[e];
    for (int e = tid; e < 22 * 262; e += 256) {
        int c = e / 262, p = e % 262;
        int l = l0 + p - 3;
        float v = 0.f;
        if ((unsigned)l < (unsigned)LQ) v = g_xdbl[((long)b * 22 + c) * LQ + l];
        sIn[c][p] = v;
    }
    __syncthreads();

    int l = l0 + tid;
    float r[22];
#pragma unroll
    for (int c = 0; c < 22; c++) {
        float acc = sbc[c];
#pragma unroll
        for (int k = 0; k < 7; k++) acc += sIn[c][tid + k] * sWc[c * 7 + k];
        r[c] = acc;
    }
    float* dout = g_delta + (long)b * 192 * LQ + l;
    for (int d = 0; d < 192; d++) {
        float s = sBd[d];
#pragma unroll
        for (int rr = 0; rr < 6; rr++) s += sWd[d * 6 + rr] * r[rr];
        float sp = (s > 20.f) ? s : log1pf(expf(s));
        dout[(long)d * LQ] = sp;
    }
    float* o = g_BC + ((long)b * LQ + l) * 16;
    float bs[8], cs[8];
#pragma unroll
    for (int n = 0; n < 8; n++) {
        bs[n] = r[6 + n]  * g_yL[((long)b * 8 + n) * LQ + l] + 1e-6f;
        cs[n] = r[14 + n] * g_ym[((long)b * 8 + n) * LQ + l] + 1e-6f;
    }
    ((float4*)o)[0] = make_float4(bs[0], bs[1], bs[2], bs[3]);
    ((float4*)o)[1] = make_float4(bs[4], bs[5], bs[6], bs[7]);
    ((float4*)o)[2] = make_float4(cs[0], cs[1], cs[2], cs[3]);
    ((float4*)o)[3] = make_float4(cs[4], cs[5], cs[6], cs[7]);
}

// ---------------- selective scan ----------------
__device__ __forceinline__ void make_powers(float q, float* p)
{
    float q2 = q * q;
    float q4 = q2 * q2;
    p[0] = q;       p[1] = q2;      p[2] = q2 * q;  p[3] = q4;
    p[4] = q4 * q;  p[5] = q4 * q2; p[6] = p[5] * q; p[7] = q4 * q4;
}

__global__ void scan_kernel(const float* __restrict__ Ds)
{
    extern __shared__ float sm[];
    float* sDelta = sm;
    float* sU = sm + 4096;
    float* sScan = sm + 8192;
    int bd = blockIdx.x;
    int b = bd / 192, d = bd % 192;
    int tid = threadIdx.x;
    const float* dp = g_delta + ((long)b * 192 + d) * LQ;
    const float* up = g_xc    + ((long)b * 192 + d) * LQ;
    for (int e = tid; e < LQ; e += 256) { sDelta[e] = dp[e]; sU[e] = up[e]; }
    float An[8];
#pragma unroll
    for (int n = 0; n < 8; n++) An[n] = g_A[d * 8 + n];
    bool powok = (g_pow_ok != 0);
    __syncthreads();
    const float* bc = g_BC + (long)b * LQ * 16;

    float a[8], hh[8];
#pragma unroll
    for (int n = 0; n < 8; n++) { a[n] = 1.f; hh[n] = 0.f; }
    int base = tid * 16;
    for (int i = 0; i < 16; i++) {
        int l = base + i;
        float delta = sDelta[l];
        float du = delta * sU[l];
        const float4* bc4 = (const float4*)(bc + (long)l * 16);
        float4 b0 = bc4[0], b1 = bc4[1];
        float bl[8] = {b0.x,b0.y,b0.z,b0.w,b1.x,b1.y,b1.z,b1.w};
        float p[8];
        if (powok) {
            make_powers(__expf(delta * An[0]), p);
        } else {
#pragma unroll
            for (int n = 0; n < 8; n++) p[n] = __expf(delta * An[n]);
        }
#pragma unroll
        for (int n = 0; n < 8; n++) {
            hh[n] = p[n] * hh[n] + du * bl[n];
            a[n] *= p[n];
        }
    }
#pragma unroll
    for (int n = 0; n < 8; n++) { sScan[n * 256 + tid] = a[n]; sScan[2048 + n * 256 + tid] = hh[n]; }
    __syncthreads();

    for (int off = 1; off < 256; off <<= 1) {
        float pa[8], pb[8];
        if (tid >= off) {
#pragma unroll
            for (int n = 0; n < 8; n++) {
                pa[n] = sScan[n * 256 + tid - off];
                pb[n] = sScan[2048 + n * 256 + tid - off];
            }
        }
        __syncthreads();
        if (tid >= off) {
#pragma unroll
            for (int n = 0; n < 8; n++) {
                float a2 = sScan[n * 256 + tid];
                float b2 = sScan[2048 + n * 256 + tid];
                sScan[n * 256 + tid] = pa[n] * a2;
                sScan[2048 + n * 256 + tid] = a2 * pb[n] + b2;
            }
        }
        __syncthreads();
    }
    float h0[8];
#pragma unroll
    for (int n = 0; n < 8; n++) h0[n] = (tid == 0) ? 0.f : sScan[2048 + n * 256 + tid - 1];
    __syncthreads();

    float Dd = Ds[d];
    for (int i = 0; i < 16; i++) {
        int l = base + i;
        float delta = sDelta[l];
        float u = sU[l];
        float du = delta * u;
        const float4* bc4 = (const float4*)(bc + (long)l * 16);
        float4 b0 = bc4[0], b1 = bc4[1], c0 = bc4[2], c1 = bc4[3];
        float bl[8] = {b0.x,b0.y,b0.z,b0.w,b1.x,b1.y,b1.z,b1.w};
        float cl[8] = {c0.x,c0.y,c0.z,c0.w,c1.x,c1.y,c1.z,c1.w};
        float p[8];
        if (powok) {
            make_powers(__expf(delta * An[0]), p);
        } else {
#pragma unroll
            for (int n = 0; n < 8; n++) p[n] = __expf(delta * An[n]);
        }
        float y = Dd * u;
#pragma unroll
        for (int n = 0; n < 8; n++) {
            h0[n] = p[n] * h0[n] + du * bl[n];
            y += h0[n] * cl[n];
        }
        sScan[l] = y;
    }
    __syncthreads();
    float* yo = g_y + ((long)b * 192 + d) * LQ;
    for (int e = tid; e < LQ; e += 256) yo[e] = sScan[e];
}

// ---------------- LayerNorm + silu(z) gate ----------------
__global__ void ln_kernel(const float* __restrict__ gamma, const float* __restrict__ beta)
{
    __shared__ float sg[192], sb2[192];
    int tid = threadIdx.x;
    for (int e = tid; e < 192; e += 256) { sg[e] = gamma[e]; sb2[e] = beta[e]; }
    __syncthreads();
    int l = blockIdx.x * 256 + tid;
    int b = blockIdx.y;
    const float* yp = g_y + (long)b * 192 * LQ + l;
    float s = 0.f, ss = 0.f;
    for (int dd = 0; dd < 192; dd++) {
        float v = yp[(long)dd * LQ];
        s += v; ss += v * v;
    }
    float mu = s * (1.f / 192.f);
    float var = ss * (1.f / 192.f) - mu * mu;
    float rs = rsqrtf(var + 1e-5f);
    const float* zp = g_zsil + (long)b * 192 * LQ + l;
    float* op = g_yn + (long)b * 192 * LQ + l;
    for (int dd = 0; dd < 192; dd++) {
        float v = (yp[(long)dd * LQ] - mu) * rs * sg[dd] + sb2[dd];
        op[(long)dd * LQ] = v * zp[(long)dd * LQ];
    }
}

// ---------------- host launcher ----------------
extern "C" void kernel_launch(void* const* d_in, const int* in_sizes, int n_in,
                              void* d_out, int out_size)
{
    const float* x        = (const float*)d_in[0];
    const float* W_in     = (const float*)d_in[1];
    const float* W_dwc_i  = (const float*)d_in[2];
    const float* b_dwc_i  = (const float*)d_in[3];
    const float* W_dw3    = (const float*)d_in[4];
    const float* b_dw3    = (const float*)d_in[5];
    const float* W_dw5    = (const float*)d_in[6];
    const float* b_dw5    = (const float*)d_in[7];
    const float* W_dw7    = (const float*)d_in[8];
    const float* b_dw7    = (const float*)d_in[9];
    const float* W_dwc_f  = (const float*)d_in[10];
    const float* b_dwc_f  = (const float*)d_in[11];
    const float* W_conv2d = (const float*)d_in[12];
    const float* b_conv2d = (const float*)d_in[13];
    const float* W_haar   = (const float*)d_in[14];
    const float* x_proj_w = (const float*)d_in[15];
    const float* W_xconv  = (const float*)d_in[16];
    const float* b_xconv  = (const float*)d_in[17];
    const float* dt_w     = (const float*)d_in[18];
    const float* dt_b     = (const float*)d_in[19];
    const float* A_logs   = (const float*)d_in[20];
    const float* Ds       = (const float*)d_in[21];
    const float* ln_g     = (const float*)d_in[22];
    const float* ln_b     = (const float*)d_in[23];
    const float* W_out    = (const float*)d_in[24];
    float* out = (float*)d_out;

    float *p_xz, *p_t, *p_t2, *p_zsil, *p_xc, *p_xdbl, *p_yn;
    cudaGetSymbolAddress((void**)&p_xz, g_xz);
    cudaGetSymbolAddress((void**)&p_t, g_t);
    cudaGetSymbolAddress((void**)&p_t2, g_t2);
    cudaGetSymbolAddress((void**)&p_zsil, g_zsil);
    cudaGetSymbolAddress((void**)&p_xc, g_xc);
    cudaGetSymbolAddress((void**)&p_xdbl, g_xdbl);
    cudaGetSymbolAddress((void**)&p_yn, g_yn);

    const int SMEM_SPLIT = (2*SW_WORDS + 2*SA_WORDS) * 4;  // 61696
    const int SMEM_PLAIN = (SW_WORDS + SA_WORDS) * 4;      // 30848
    cudaFuncSetAttribute((const void*)gemm_tf32_kernel<true, 0>,
                         cudaFuncAttributeMaxDynamicSharedMemorySize, SMEM_SPLIT);
    cudaFuncSetAttribute((const void*)gemm_tf32_kernel<false, 1>,
                         cudaFuncAttributeMaxDynamicSharedMemorySize, SMEM_PLAIN);
    cudaFuncSetAttribute((const void*)gemm_tf32_kernel<false, 2>,
                         cudaFuncAttributeMaxDynamicSharedMemorySize, SMEM_PLAIN);
    cudaFuncSetAttribute(haar_kernel, cudaFuncAttributeMaxDynamicSharedMemorySize, 73728);
    cudaFuncSetAttribute(scan_kernel, cudaFuncAttributeMaxDynamicSharedMemorySize, 49152);

    static cudaStream_t sZ = nullptr;
    static cudaEvent_t evFork = nullptr, evJoin = nullptr;
    if (!sZ) {
        cudaStreamCreateWithFlags(&sZ, cudaStreamNonBlocking);
        cudaEventCreateWithFlags(&evFork, cudaEventDisableTiming);
        cudaEventCreateWithFlags(&evJoin, cudaEventDisableTiming);
    }

    prep_kernel<<<6, 256>>>(A_logs);
    prep2_kernel<<<1, 256>>>();

    gemm_tf32_kernel<true, 0><<<dim3(32, 6, NB), 256, SMEM_SPLIT>>>(
        x, 96L * LQ, W_in, nullptr, p_xz, nullptr, 384L * LQ, 384, 96);

    // ---- fork: z branch on stream sZ ----
    cudaEventRecord(evFork, 0);
    cudaStreamWaitEvent(sZ, evFork, 0);

    gemm_tf32_kernel<false, 1><<<dim3(32, 6, NB), 256, SMEM_PLAIN, sZ>>>(
        p_xz + 192L * LQ, 384L * LQ, W_dwc_i, b_dwc_i, p_t, p_t2, 384L * LQ, 384, 192);
    dwconv_all_kernel<<<dim3(288, NB), 256, 0, sZ>>>(W_dw3, b_dw3, W_dw5, b_dw5, W_dw7, b_dw7);
    gemm_tf32_kernel<false, 2><<<dim3(32, 3, NB), 256, SMEM_PLAIN, sZ>>>(
        p_t2, 384L * LQ, W_dwc_f, b_dwc_f, p_zsil, nullptr, 192L * LQ, 192, 384);
    cudaEventRecord(evJoin, sZ);

    // ---- x branch on default stream ----
    dw3_silu_kernel<<<dim3(192, NB), 256>>>(W_conv2d, b_conv2d);
    haar_kernel<<<dim3(32, NB), 256, 73728>>>(W_haar);
    gemm_tf32_kernel<true, 0><<<dim3(32, 1, NB), 256, SMEM_SPLIT>>>(
        p_xc, 192L * LQ, x_proj_w, nullptr, p_xdbl, nullptr, 22L * LQ, 22, 192);
    convdtbc_kernel<<<dim3(16, NB), 256>>>(W_xconv, b_xconv, dt_w, dt_b);
    scan_kernel<<<NB * 192, 256, 49152>>>(Ds);

    // ---- join, then LN + output GEMM ----
    cudaStreamWaitEvent(0, evJoin, 0);
    ln_kernel<<<dim3(16, NB), 256>>>(ln_g, ln_b);
    gemm_tf32_kernel<true, 0><<<dim3(32, 2, NB), 256, SMEM_SPLIT>>>(
        p_yn, 192L * LQ, W_out, nullptr, out, nullptr, 96L * LQ, 96, 192);
    (void)in_sizes; (void)n_in; (void)out_size;
}

// round 11
// speedup vs baseline: 1.2049x; 1.2049x over previous
#include <cuda_runtime.h>
#include <cuda_bf16.h>
#include <stdint.h>
#include <math.h>

#define NB 8
#define LQ 4096

// ---------------- device scratch (zero-init BSS, no allocation) ----------------
__device__ float g_xz   [(long)NB*384*LQ];
__device__ float g_t    [(long)NB*384*LQ];
__device__ float g_t2   [(long)NB*384*LQ];
__device__ float g_zsil [(long)NB*192*LQ];
__device__ float g_xc   [(long)NB*192*LQ];
__device__ float g_yL   [(long)NB*8*LQ];
__device__ float g_ym   [(long)NB*8*LQ];
__device__ float g_xdbl [(long)NB*22*LQ];
__device__ float g_delta[(long)NB*192*LQ];
__device__ float g_BC   [(long)NB*LQ*16];
__device__ float g_y    [(long)NB*192*LQ];
__device__ float g_yn   [(long)NB*192*LQ];
__device__ float g_A    [192*8];
__device__ int   g_pow_ok;

// ---------------- prep ----------------
__global__ void prep_kernel(const float* __restrict__ Alogs)
{
    int t = blockIdx.x * 256 + threadIdx.x;
    if (t < 192*8) g_A[t] = -expf(Alogs[t]);
}

__global__ void prep2_kernel()
{
    __shared__ int ok;
    if (threadIdx.x == 0) ok = 1;
    __syncthreads();
    for (int d = threadIdx.x; d < 192; d += 256) {
        float a0 = g_A[d * 8];
        for (int n = 1; n < 8; n++) {
            float expect = a0 * (float)(n + 1);
            float got = g_A[d * 8 + n];
            if (fabsf(got - expect) > 1e-5f * fabsf(expect)) atomicAnd(&ok, 0);
        }
    }
    __syncthreads();
    if (threadIdx.x == 0) g_pow_ok = ok;
}

__device__ __forceinline__ float gelu_exact(float v)
{
    return 0.5f * v * (1.f + erff(v * 0.70710678118654752f));
}

// ---------------- common MMA helpers ----------------
__device__ __forceinline__ uint32_t f2tf32(float f)
{
    uint32_t o;
    asm("cvt.rna.tf32.f32 %0, %1;" : "=r"(o) : "f"(f));
    return o;
}

__device__ __forceinline__ uint32_t bits2tf32(uint32_t w)
{
    uint32_t o;
    asm("cvt.rna.tf32.f32 %0, %1;" : "=r"(o) : "f"(__uint_as_float(w)));
    return o;
}

__device__ __forceinline__ void mma_tf32(float* d, const uint32_t* a, const uint32_t* b)
{
    asm volatile("mma.sync.aligned.m16n8k8.row.col.f32.tf32.tf32.f32 "
                 "{%0,%1,%2,%3}, {%4,%5,%6,%7}, {%8,%9}, {%0,%1,%2,%3};"
                 : "+f"(d[0]), "+f"(d[1]), "+f"(d[2]), "+f"(d[3])
                 : "r"(a[0]), "r"(a[1]), "r"(a[2]), "r"(a[3]),
                   "r"(b[0]), "r"(b[1]));
}

__device__ __forceinline__ void epi_store(float* Ob, float* O2b, int n, int m, float v, int EPI)
{
    if (EPI == 1) {
        if (n < 96) O2b[(long)n * LQ + m] = gelu_exact(v);
        else        Ob [(long)n * LQ + m] = v;
    } else if (EPI == 2) {
        int tr = ((m & 63) << 6) | (m >> 6);
        Ob[(long)n * LQ + tr] = v / (1.f + __expf(-v));
    } else {
        Ob[(long)n * LQ + m] = v;
    }
}

__device__ __forceinline__ void cpa16(uint32_t dst, const float* src)
{
    asm volatile("cp.async.cg.shared.global [%0], [%1], 16;" :: "r"(dst), "l"(src));
}

// ---------------- split tf32 GEMM (R7-proven layout: sW[64][36], sA[32][136]) --------
__global__ void __launch_bounds__(256)
gemm_tf32_split_kernel(const float* __restrict__ Act, long actStride,
                       const float* __restrict__ W, const float* __restrict__ bias,
                       float* __restrict__ O, long oStride, int N, int K)
{
    extern __shared__ uint32_t dsm[];
    uint32_t* sWb = dsm;
    uint32_t* sWs = dsm + 64*36;
    uint32_t* sAb = dsm + 2*64*36;
    uint32_t* sAs = sAb + 32*136;

    const float* Ab = Act + (long)blockIdx.z * actStride;
    float* Ob = O + (long)blockIdx.z * oStride;
    int m0 = blockIdx.x * 128, n0 = blockIdx.y * 64;
    int tid = threadIdx.x, lane = tid & 31, wid = tid >> 5;
    int wn = (wid & 1) * 32;
    int wm = (wid >> 1) * 32;

    float d[2][4][4];
#pragma unroll
    for (int i = 0; i < 2; i++)
#pragma unroll
        for (int j = 0; j < 4; j++)
#pragma unroll
            for (int q = 0; q < 4; q++) d[i][j][q] = 0.f;

    for (int kc = 0; kc < K; kc += 32) {
#pragma unroll
        for (int i = 0; i < 2; i++) {
            int e = tid + i * 256;
            int row = e >> 3, c4 = (e & 7) * 4;
            int n = n0 + row;
            float4 v = make_float4(0.f, 0.f, 0.f, 0.f);
            if (n < N) v = *(const float4*)(W + (long)n * K + kc + c4);
            float vv[4] = {v.x, v.y, v.z, v.w};
#pragma unroll
            for (int t = 0; t < 4; t++) {
                uint32_t bg = f2tf32(vv[t]);
                sWb[row * 36 + c4 + t] = bg;
                sWs[row * 36 + c4 + t] = f2tf32(vv[t] - __uint_as_float(bg));
            }
        }
#pragma unroll
        for (int i = 0; i < 4; i++) {
            int e = tid + i * 256;
            int row = e >> 5, c4 = (e & 31) * 4;
            float4 v = *(const float4*)(Ab + (long)(kc + row) * LQ + m0 + c4);
            float vv[4] = {v.x, v.y, v.z, v.w};
#pragma unroll
            for (int t = 0; t < 4; t++) {
                uint32_t bg = f2tf32(vv[t]);
                sAb[row * 136 + c4 + t] = bg;
                sAs[row * 136 + c4 + t] = f2tf32(vv[t] - __uint_as_float(bg));
            }
        }
        __syncthreads();

#pragma unroll
        for (int ks = 0; ks < 4; ks++) {
            int kk = ks * 8;
            uint32_t afrB[2][4], bfrB[4][2];
            uint32_t afrS[2][4], bfrS[4][2];
            int r = wn + (lane >> 2);
            int c = kk + (lane & 3);
#pragma unroll
            for (int i = 0; i < 2; i++) {
                int rb = r + i * 16;
                afrB[i][0] = sWb[rb * 36 + c];
                afrB[i][1] = sWb[(rb + 8) * 36 + c];
                afrB[i][2] = sWb[rb * 36 + c + 4];
                afrB[i][3] = sWb[(rb + 8) * 36 + c + 4];
                afrS[i][0] = sWs[rb * 36 + c];
                afrS[i][1] = sWs[(rb + 8) * 36 + c];
                afrS[i][2] = sWs[rb * 36 + c + 4];
                afrS[i][3] = sWs[(rb + 8) * 36 + c + 4];
            }
            int mcol = wm + (lane >> 2);
            int krow = kk + (lane & 3);
#pragma unroll
            for (int j = 0; j < 4; j++) {
                bfrB[j][0] = sAb[krow * 136 + mcol + j * 8];
                bfrB[j][1] = sAb[(krow + 4) * 136 + mcol + j * 8];
                bfrS[j][0] = sAs[krow * 136 + mcol + j * 8];
                bfrS[j][1] = sAs[(krow + 4) * 136 + mcol + j * 8];
            }
#pragma unroll
            for (int i = 0; i < 2; i++)
#pragma unroll
                for (int j = 0; j < 4; j++) {
                    mma_tf32(d[i][j], afrB[i], bfrS[j]);
                    mma_tf32(d[i][j], afrS[i], bfrB[j]);
                    mma_tf32(d[i][j], afrB[i], bfrB[j]);
                }
        }
        __syncthreads();
    }

#pragma unroll
    for (int i = 0; i < 2; i++) {
        int n = n0 + wn + i * 16 + (lane >> 2);
        float bb0 = (bias && n < N) ? bias[n] : 0.f;
        float bb1 = (bias && n + 8 < N) ? bias[n + 8] : 0.f;
#pragma unroll
        for (int j = 0; j < 4; j++) {
            int m = m0 + wm + j * 8 + 2 * (lane & 3);
            if (n < N) {
                float* p0 = Ob + (long)n * LQ + m;
                p0[0] = d[i][j][0] + bb0;
                p0[1] = d[i][j][1] + bb0;
            }
            if (n + 8 < N) {
                float* p1 = Ob + (long)(n + 8) * LQ + m;
                p1[0] = d[i][j][2] + bb1;
                p1[1] = d[i][j][3] + bb1;
            }
        }
    }
}

// ---------------- plain tf32 GEMM with cp.async double-buffered pipeline --------------
// Raw fp32 bits land in smem via cp.async; fragments are converted with cvt.rna
// AFTER the smem load (restores round-to-nearest => R7-level accuracy).
// Requires N % 64 == 0 (K2: N=384, K4: N=192).
#define WB_WORDS (64*36)   // 2304
#define AB_WORDS (32*136)  // 4352

template<int EPI>
__global__ void __launch_bounds__(256)
gemm_tf32_pipe_kernel(const float* __restrict__ Act, long actStride,
                      const float* __restrict__ W, const float* __restrict__ bias,
                      float* __restrict__ O, float* __restrict__ O2,
                      long oStride, int N, int K)
{
    extern __shared__ uint32_t dsm[];
    const float* Ab = Act + (long)blockIdx.z * actStride;
    float* Ob = O + (long)blockIdx.z * oStride;
    float* O2b = O2 ? (O2 + (long)blockIdx.z * oStride) : nullptr;
    int m0 = blockIdx.x * 128, n0 = blockIdx.y * 64;
    int tid = threadIdx.x, lane = tid & 31, wid = tid >> 5;
    int wn = (wid & 1) * 32;
    int wm = (wid >> 1) * 32;

    uint32_t smem_base = (uint32_t)__cvta_generic_to_shared(dsm);

    float d[2][4][4];
#pragma unroll
    for (int i = 0; i < 2; i++)
#pragma unroll
        for (int j = 0; j < 4; j++)
#pragma unroll
            for (int q = 0; q < 4; q++) d[i][j][q] = 0.f;

    int wr0 = tid >> 3, wj = (tid & 7) * 4;

    auto issue_tile = [&](int buf, int kc) {
#pragma unroll
        for (int i = 0; i < 2; i++) {
            int row = wr0 + i * 32;
            uint32_t dst = smem_base + (buf * WB_WORDS + row * 36 + wj) * 4;
            cpa16(dst, W + (long)(n0 + row) * K + kc + wj);
        }
#pragma unroll
        for (int i = 0; i < 4; i++) {
            int e = tid + i * 256;
            int kk = e >> 5, c4 = (e & 31) * 4;
            uint32_t dst = smem_base + (2 * WB_WORDS + buf * AB_WORDS + kk * 136 + c4) * 4;
            cpa16(dst, Ab + (long)(kc + kk) * LQ + m0 + c4);
        }
        asm volatile("cp.async.commit_group;" ::: "memory");
    };

    int nT = K >> 5;
    issue_tile(0, 0);
    for (int kt = 0; kt < nT; kt++) {
        int cur = kt & 1;
        if (kt + 1 < nT) {
            issue_tile(cur ^ 1, (kt + 1) << 5);
            asm volatile("cp.async.wait_group 1;" ::: "memory");
        } else {
            asm volatile("cp.async.wait_group 0;" ::: "memory");
        }
        __syncthreads();

        const uint32_t* sWc = dsm + cur * WB_WORDS;
        const uint32_t* sAc = dsm + 2 * WB_WORDS + cur * AB_WORDS;
#pragma unroll
        for (int ks = 0; ks < 4; ks++) {
            int kk = ks * 8;
            uint32_t afr[2][4], bfr[4][2];
            int r = wn + (lane >> 2);
            int c = kk + (lane & 3);
#pragma unroll
            for (int i = 0; i < 2; i++) {
                int rb = r + i * 16;
                afr[i][0] = bits2tf32(sWc[rb * 36 + c]);
                afr[i][1] = bits2tf32(sWc[(rb + 8) * 36 + c]);
                afr[i][2] = bits2tf32(sWc[rb * 36 + c + 4]);
                afr[i][3] = bits2tf32(sWc[(rb + 8) * 36 + c + 4]);
            }
            int mcol = wm + (lane >> 2);
            int krow = kk + (lane & 3);
#pragma unroll
            for (int j = 0; j < 4; j++) {
                bfr[j][0] = bits2tf32(sAc[krow * 136 + mcol + j * 8]);
                bfr[j][1] = bits2tf32(sAc[(krow + 4) * 136 + mcol + j * 8]);
            }
#pragma unroll
            for (int i = 0; i < 2; i++)
#pragma unroll
                for (int j = 0; j < 4; j++)
                    mma_tf32(d[i][j], afr[i], bfr[j]);
        }
        __syncthreads();
    }

#pragma unroll
    for (int i = 0; i < 2; i++) {
        int n = n0 + wn + i * 16 + (lane >> 2);
        float bb0 = bias ? bias[n] : 0.f;
        float bb1 = bias ? bias[n + 8] : 0.f;
#pragma unroll
        for (int j = 0; j < 4; j++) {
            int m = m0 + wm + j * 8 + 2 * (lane & 3);
            epi_store(Ob, O2b, n, m,         d[i][j][0] + bb0, EPI);
            epi_store(Ob, O2b, n, m + 1,     d[i][j][1] + bb0, EPI);
            epi_store(Ob, O2b, n + 8, m,     d[i][j][2] + bb1, EPI);
            epi_store(Ob, O2b, n + 8, m + 1, d[i][j][3] + bb1, EPI);
        }
    }
}

// ---------------- z branch: merged multi-scale depthwise conv + GELU ----------------
template<int KSZ>
__device__ __forceinline__ void dwconv_body(float* sm, const float* __restrict__ W,
                                            const float* __restrict__ bias,
                                            int c, int b, int co)
{
    constexpr int PAD = KSZ / 2;
    constexpr int SH = 64 + 2 * PAD;
    int tid = threadIdx.x;
    const float* src = g_t + ((long)b * 384 + co) * LQ;

    for (int e = tid; e < SH * 72; e += 256) sm[e] = 0.f;
    __syncthreads();
    for (int e = tid; e < LQ; e += 256) {
        int h = e >> 6, w = e & 63;
        sm[(h + PAD) * 72 + (w + PAD)] = src[e];
    }
    __syncthreads();

    float wreg[KSZ * KSZ];
#pragma unroll
    for (int i = 0; i < KSZ * KSZ; i++) wreg[i] = W[c * KSZ * KSZ + i];
    float bb = bias[c];

    float* dst = g_t2 + ((long)b * 384 + co) * LQ;
    for (int e = tid; e < LQ; e += 256) {
        int h = e >> 6, w = e & 63;
        float acc = bb;
#pragma unroll
        for (int ky = 0; ky < KSZ; ky++) {
            const float* row = sm + (h + ky) * 72 + w;
#pragma unroll
            for (int kx = 0; kx < KSZ; kx++)
                acc += row[kx] * wreg[ky * KSZ + kx];
        }
        dst[e] = gelu_exact(acc);
    }
}

__global__ void dwconv_all_kernel(const float* __restrict__ W3, const float* __restrict__ b3,
                                  const float* __restrict__ W5, const float* __restrict__ b5,
                                  const float* __restrict__ W7, const float* __restrict__ b7)
{
    __shared__ float sm[70 * 72];
    int cc = blockIdx.x;
    int b = blockIdx.y;
    if (cc < 96)       dwconv_body<3>(sm, W3, b3, cc,        b,  96 + cc);
    else if (cc < 192) dwconv_body<5>(sm, W5, b5, cc - 96,   b, 192 + (cc - 96));
    else               dwconv_body<7>(sm, W7, b7, cc - 192,  b, 288 + (cc - 192));
}

// ---------------- x branch: depthwise 3x3 + bias + silu ----------------
__global__ void dw3_silu_kernel(const float* __restrict__ W, const float* __restrict__ bias)
{
    __shared__ float sm[66 * 68];
    int c = blockIdx.x;
    int b = blockIdx.y;
    int tid = threadIdx.x;
    const float* src = g_xz + ((long)b * 384 + c) * LQ;
    for (int e = tid; e < 66 * 68; e += 256) sm[e] = 0.f;
    __syncthreads();
    for (int e = tid; e < LQ; e += 256) {
        int h = e >> 6, w = e & 63;
        sm[(h + 1) * 68 + (w + 1)] = src[e];
    }
    __syncthreads();
    float w0 = W[c*9+0], w1 = W[c*9+1], w2 = W[c*9+2];
    float w3 = W[c*9+3], w4 = W[c*9+4], w5 = W[c*9+5];
    float w6 = W[c*9+6], w7 = W[c*9+7], w8 = W[c*9+8];
    float bb = bias[c];
    float* dst = g_xc + ((long)b * 192 + c) * LQ;
    for (int e = tid; e < LQ; e += 256) {
        int h = e >> 6, w = e & 63;
        const float* r0 = sm + h * 68 + w;
        float acc = bb + r0[0]*w0 + r0[1]*w1 + r0[2]*w2
                       + r0[68]*w3 + r0[69]*w4 + r0[70]*w5
                       + r0[136]*w6 + r0[137]*w7 + r0[138]*w8;
        dst[e] = acc / (1.f + __expf(-acc));
    }
}

// ---------------- haar 1x1 conv + strided combine -> yL, y_mean ----------------
__global__ void haar_kernel(const float* __restrict__ Wh)
{
    extern __shared__ float smh[];
    float* sW = smh;
    float* s1 = smh + 32 * 192;
    float* s2 = s1 + 192 * 32;
    int i = blockIdx.x, b = blockIdx.y;
    int tid = threadIdx.x;
    for (int e = tid; e < 32 * 192; e += 256) sW[e] = Wh[e];
    const float* xcb = g_xc + (long)b * 192 * LQ;
    for (int e = tid; e < 192 * 32; e += 256) {
        int d = e >> 5, j = e & 31;
        const float* row0 = xcb + (long)d * LQ + (2 * i) * 64 + 2 * j;
        float xa = row0[0], xb = row0[1];
        float xc2 = row0[64], xd = row0[65];
        s1[d * 32 + j] = xa + xb + xc2 + xd;
        s2[d * 32 + j] = 3.f * xa - xb - xc2 - xd;
    }
    __syncthreads();
    for (int e = tid; e < 2048; e += 256) {
        int which = e >> 10;
        int ch = (e >> 5) & 31;
        int j = e & 31;
        const float* sv = (which ? s2 : s1) + j;
        const float* wr = sW + ch * 192;
        float acc = 0.f;
#pragma unroll 4
        for (int d = 0; d < 192; d++) acc += wr[d] * sv[d * 32];
        acc *= which ? (1.f / 6.f) : 0.5f;
        int n = ch >> 2;
        int lpos = (ch & 3) * 1024 + i * 32 + j;
        float* dst = which ? g_ym : g_yL;
        dst[((long)b * 8 + n) * LQ + lpos] = acc;
    }
}

// ---------------- fused: conv1d(k=7) + dt projection + softplus + B/C assembly --------
__global__ void convdtbc_kernel(const float* __restrict__ Wx, const float* __restrict__ bx,
                                const float* __restrict__ Wdt, const float* __restrict__ dtb)
{
    __shared__ float sIn[22][264];
    __shared__ float sWd[192 * 6];
    __shared__ float sBd[192];
    __shared__ float sWc[22 * 7];
    __shared__ float sbc[22];
    int tid = threadIdx.x;
    int l0 = blockIdx.x * 256;
    int b = blockIdx.y;

    for (int e = tid; e < 1152; e += 256) sWd[e] = Wdt[e];
    for (int e = tid; e < 192; e += 256) sBd[e] = dtb[e];
    for (int e = tid; e < 154; e += 256) sWc[e] = Wx[e];
    for (int e = tid; e < 22; e += 256) sbc[e] = bx[e];
    for (int e = tid; e < 22 * 262; e += 256) {
        int c = e / 262, p = e % 262;
        int l = l0 + p - 3;
        float v = 0.f;
        if ((unsigned)l < (unsigned)LQ) v = g_xdbl[((long)b * 22 + c) * LQ + l];
        sIn[c][p] = v;
    }
    __syncthreads();

    int l = l0 + tid;
    float r[22];
#pragma unroll
    for (int c = 0; c < 22; c++) {
        float acc = sbc[c];
#pragma unroll
        for (int k = 0; k < 7; k++) acc += sIn[c][tid + k] * sWc[c * 7 + k];
        r[c] = acc;
    }
    float* dout = g_delta + (long)b * 192 * LQ + l;
    for (int d = 0; d < 192; d++) {
        float s = sBd[d];
#pragma unroll
        for (int rr = 0; rr < 6; rr++) s += sWd[d * 6 + rr] * r[rr];
        float sp = (s > 20.f) ? s : log1pf(expf(s));
        dout[(long)d * LQ] = sp;
    }
    float* o = g_BC + ((long)b * LQ + l) * 16;
    float bs[8], cs[8];
#pragma unroll
    for (int n = 0; n < 8; n++) {
        bs[n] = r[6 + n]  * g_yL[((long)b * 8 + n) * LQ + l] + 1e-6f;
        cs[n] = r[14 + n] * g_ym[((long)b * 8 + n) * LQ + l] + 1e-6f;
    }
    ((float4*)o)[0] = make_float4(bs[0], bs[1], bs[2], bs[3]);
    ((float4*)o)[1] = make_float4(bs[4], bs[5], bs[6], bs[7]);
    ((float4*)o)[2] = make_float4(cs[0], cs[1], cs[2], cs[3]);
    ((float4*)o)[3] = make_float4(cs[4], cs[5], cs[6], cs[7]);
}

// ---------------- selective scan ----------------
__device__ __forceinline__ void make_powers(float q, float* p)
{
    float q2 = q * q;
    float q4 = q2 * q2;
    p[0] = q;       p[1] = q2;      p[2] = q2 * q;  p[3] = q4;
    p[4] = q4 * q;  p[5] = q4 * q2; p[6] = p[5] * q; p[7] = q4 * q4;
}

__global__ void scan_kernel(const float* __restrict__ Ds)
{
    extern __shared__ float sm[];
    float* sDelta = sm;
    float* sU = sm + 4096;
    float* sScan = sm + 8192;
    int bd = blockIdx.x;
    int b = bd / 192, d = bd % 192;
    int tid = threadIdx.x;
    const float* dp = g_delta + ((long)b * 192 + d) * LQ;
    const float* up = g_xc    + ((long)b * 192 + d) * LQ;
    for (int e = tid; e < LQ; e += 256) { sDelta[e] = dp[e]; sU[e] = up[e]; }
    float An[8];
#pragma unroll
    for (int n = 0; n < 8; n++) An[n] = g_A[d * 8 + n];
    bool powok = (g_pow_ok != 0);
    __syncthreads();
    const float* bc = g_BC + (long)b * LQ * 16;

    float a[8], hh[8];
#pragma unroll
    for (int n = 0; n < 8; n++) { a[n] = 1.f; hh[n] = 0.f; }
    int base = tid * 16;
    for (int i = 0; i < 16; i++) {
        int l = base + i;
        float delta = sDelta[l];
        float du = delta * sU[l];
        const float4* bc4 = (const float4*)(bc + (long)l * 16);
        float4 b0 = bc4[0], b1 = bc4[1];
        float bl[8] = {b0.x,b0.y,b0.z,b0.w,b1.x,b1.y,b1.z,b1.w};
        float p[8];
        if (powok) {
            make_powers(__expf(delta * An[0]), p);
        } else {
#pragma unroll
            for (int n = 0; n < 8; n++) p[n] = __expf(delta * An[n]);
        }
#pragma unroll
        for (int n = 0; n < 8; n++) {
            hh[n] = p[n] * hh[n] + du * bl[n];
            a[n] *= p[n];
        }
    }
#pragma unroll
    for (int n = 0; n < 8; n++) { sScan[n * 256 + tid] = a[n]; sScan[2048 + n * 256 + tid] = hh[n]; }
    __syncthreads();

    for (int off = 1; off < 256; off <<= 1) {
        float pa[8], pb[8];
        if (tid >= off) {
#pragma unroll
            for (int n = 0; n < 8; n++) {
                pa[n] = sScan[n * 256 + tid - off];
                pb[n] = sScan[2048 + n * 256 + tid - off];
            }
        }
        __syncthreads();
        if (tid >= off) {
#pragma unroll
            for (int n = 0; n < 8; n++) {
                float a2 = sScan[n * 256 + tid];
                float b2 = sScan[2048 + n * 256 + tid];
                sScan[n * 256 + tid] = pa[n] * a2;
                sScan[2048 + n * 256 + tid] = a2 * pb[n] + b2;
            }
        }
        __syncthreads();
    }
    float h0[8];
#pragma unroll
    for (int n = 0; n < 8; n++) h0[n] = (tid == 0) ? 0.f : sScan[2048 + n * 256 + tid - 1];
    __syncthreads();

    float Dd = Ds[d];
    for (int i = 0; i < 16; i++) {
        int l = base + i;
        float delta = sDelta[l];
        float u = sU[l];
        float du = delta * u;
        const float4* bc4 = (const float4*)(bc + (long)l * 16);
        float4 b0 = bc4[0], b1 = bc4[1], c0 = bc4[2], c1 = bc4[3];
        float bl[8] = {b0.x,b0.y,b0.z,b0.w,b1.x,b1.y,b1.z,b1.w};
        float cl[8] = {c0.x,c0.y,c0.z,c0.w,c1.x,c1.y,c1.z,c1.w};
        float p[8];
        if (powok) {
            make_powers(__expf(delta * An[0]), p);
        } else {
#pragma unroll
            for (int n = 0; n < 8; n++) p[n] = __expf(delta * An[n]);
        }
        float y = Dd * u;
#pragma unroll
        for (int n = 0; n < 8; n++) {
            h0[n] = p[n] * h0[n] + du * bl[n];
            y += h0[n] * cl[n];
        }
        sScan[l] = y;
    }
    __syncthreads();
    float* yo = g_y + ((long)b * 192 + d) * LQ;
    for (int e = tid; e < LQ; e += 256) yo[e] = sScan[e];
}

// ---------------- LayerNorm + silu(z) gate ----------------
__global__ void ln_kernel(const float* __restrict__ gamma, const float* __restrict__ beta)
{
    __shared__ float sg[192], sb2[192];
    int tid = threadIdx.x;
    for (int e = tid; e < 192; e += 256) { sg[e] = gamma[e]; sb2[e] = beta[e]; }
    __syncthreads();
    int l = blockIdx.x * 256 + tid;
    int b = blockIdx.y;
    const float* yp = g_y + (long)b * 192 * LQ + l;
    float s = 0.f, ss = 0.f;
    for (int dd = 0; dd < 192; dd++) {
        float v = yp[(long)dd * LQ];
        s += v; ss += v * v;
    }
    float mu = s * (1.f / 192.f);
    float var = ss * (1.f / 192.f) - mu * mu;
    float rs = rsqrtf(var + 1e-5f);
    const float* zp = g_zsil + (long)b * 192 * LQ + l;
    float* op = g_yn + (long)b * 192 * LQ + l;
    for (int dd = 0; dd < 192; dd++) {
        float v = (yp[(long)dd * LQ] - mu) * rs * sg[dd] + sb2[dd];
        op[(long)dd * LQ] = v * zp[(long)dd * LQ];
    }
}

// ---------------- host launcher ----------------
extern "C" void kernel_launch(void* const* d_in, const int* in_sizes, int n_in,
                              void* d_out, int out_size)
{
    const float* x        = (const float*)d_in[0];
    const float* W_in     = (const float*)d_in[1];
    const float* W_dwc_i  = (const float*)d_in[2];
    const float* b_dwc_i  = (const float*)d_in[3];
    const float* W_dw3    = (const float*)d_in[4];
    const float* b_dw3    = (const float*)d_in[5];
    const float* W_dw5    = (const float*)d_in[6];
    const float* b_dw5    = (const float*)d_in[7];
    const float* W_dw7    = (const float*)d_in[8];
    const float* b_dw7    = (const float*)d_in[9];
    const float* W_dwc_f  = (const float*)d_in[10];
    const float* b_dwc_f  = (const float*)d_in[11];
    const float* W_conv2d = (const float*)d_in[12];
    const float* b_conv2d = (const float*)d_in[13];
    const float* W_haar   = (const float*)d_in[14];
    const float* x_proj_w = (const float*)d_in[15];
    const float* W_xconv  = (const float*)d_in[16];
    const float* b_xconv  = (const float*)d_in[17];
    const float* dt_w     = (const float*)d_in[18];
    const float* dt_b     = (const float*)d_in[19];
    const float* A_logs   = (const float*)d_in[20];
    const float* Ds       = (const float*)d_in[21];
    const float* ln_g     = (const float*)d_in[22];
    const float* ln_b     = (const float*)d_in[23];
    const float* W_out    = (const float*)d_in[24];
    float* out = (float*)d_out;

    float *p_xz, *p_t, *p_t2, *p_zsil, *p_xc, *p_xdbl, *p_yn;
    cudaGetSymbolAddress((void**)&p_xz, g_xz);
    cudaGetSymbolAddress((void**)&p_t, g_t);
    cudaGetSymbolAddress((void**)&p_t2, g_t2);
    cudaGetSymbolAddress((void**)&p_zsil, g_zsil);
    cudaGetSymbolAddress((void**)&p_xc, g_xc);
    cudaGetSymbolAddress((void**)&p_xdbl, g_xdbl);
    cudaGetSymbolAddress((void**)&p_yn, g_yn);

    const int SMEM_SPLIT = (2*64*36 + 2*32*136) * 4;      // 53248
    const int SMEM_PIPE  = (2*WB_WORDS + 2*AB_WORDS) * 4; // 53248
    cudaFuncSetAttribute((const void*)gemm_tf32_split_kernel,
                         cudaFuncAttributeMaxDynamicSharedMemorySize, SMEM_SPLIT);
    cudaFuncSetAttribute((const void*)gemm_tf32_pipe_kernel<1>,
                         cudaFuncAttributeMaxDynamicSharedMemorySize, SMEM_PIPE);
    cudaFuncSetAttribute((const void*)gemm_tf32_pipe_kernel<2>,
                         cudaFuncAttributeMaxDynamicSharedMemorySize, SMEM_PIPE);
    cudaFuncSetAttribute(haar_kernel, cudaFuncAttributeMaxDynamicSharedMemorySize, 73728);
    cudaFuncSetAttribute(scan_kernel, cudaFuncAttributeMaxDynamicSharedMemorySize, 49152);

    static cudaStream_t sZ = nullptr;
    static cudaEvent_t evFork = nullptr, evJoin = nullptr;
    if (!sZ) {
        cudaStreamCreateWithFlags(&sZ, cudaStreamNonBlocking);
        cudaEventCreateWithFlags(&evFork, cudaEventDisableTiming);
        cudaEventCreateWithFlags(&evJoin, cudaEventDisableTiming);
    }

    prep_kernel<<<6, 256>>>(A_logs);
    prep2_kernel<<<1, 256>>>();

    // K1: input GEMM (split tf32, ~fp32 accuracy)
    gemm_tf32_split_kernel<<<dim3(32, 6, NB), 256, SMEM_SPLIT>>>(
        x, 96L * LQ, W_in, nullptr, p_xz, 384L * LQ, 384, 96);

    // ---- fork: z branch on stream sZ ----
    cudaEventRecord(evFork, 0);
    cudaStreamWaitEvent(sZ, evFork, 0);

    // K2: z 1x1 init conv (192->384), pipelined, gelu fused for n<96
    gemm_tf32_pipe_kernel<1><<<dim3(32, 6, NB), 256, SMEM_PIPE, sZ>>>(
        p_xz + 192L * LQ, 384L * LQ, W_dwc_i, b_dwc_i, p_t, p_t2, 384L * LQ, 384, 192);
    dwconv_all_kernel<<<dim3(288, NB), 256, 0, sZ>>>(W_dw3, b_dw3, W_dw5, b_dw5, W_dw7, b_dw7);
    // K4: z final 1x1 conv (384->192), pipelined, silu+transpose fused
    gemm_tf32_pipe_kernel<2><<<dim3(32, 3, NB), 256, SMEM_PIPE, sZ>>>(
        p_t2, 384L * LQ, W_dwc_f, b_dwc_f, p_zsil, nullptr, 192L * LQ, 192, 384);
    cudaEventRecord(evJoin, sZ);

    // ---- x branch on default stream ----
    dw3_silu_kernel<<<dim3(192, NB), 256>>>(W_conv2d, b_conv2d);
    haar_kernel<<<dim3(32, NB), 256, 73728>>>(W_haar);
    gemm_tf32_split_kernel<<<dim3(32, 1, NB), 256, SMEM_SPLIT>>>(
        p_xc, 192L * LQ, x_proj_w, nullptr, p_xdbl, 22L * LQ, 22, 192);
    convdtbc_kernel<<<dim3(16, NB), 256>>>(W_xconv, b_xconv, dt_w, dt_b);
    scan_kernel<<<NB * 192, 256, 49152>>>(Ds);

    // ---- join, then LN + output GEMM ----
    cudaStreamWaitEvent(0, evJoin, 0);
    ln_kernel<<<dim3(16, NB), 256>>>(ln_g, ln_b);
    gemm_tf32_split_kernel<<<dim3(32, 2, NB), 256, SMEM_SPLIT>>>(
        p_yn, 192L * LQ, W_out, nullptr, out, 96L * LQ, 96, 192);
    (void)in_sizes; (void)n_in; (void)out_size;
}

// round 13
// speedup vs baseline: 1.3680x; 1.1354x over previous
#include <cuda_runtime.h>
#include <cuda_bf16.h>
#include <stdint.h>
#include <math.h>

#define NB 8
#define LQ 4096

// ---------------- device scratch (zero-init BSS, no allocation) ----------------
__device__ float g_xz   [(long)NB*384*LQ];
__device__ float g_t    [(long)NB*384*LQ];
__device__ float g_t2   [(long)NB*384*LQ];
__device__ float g_zsil [(long)NB*192*LQ];
__device__ float g_xc   [(long)NB*192*LQ];
__device__ float g_yL   [(long)NB*8*LQ];
__device__ float g_ym   [(long)NB*8*LQ];
__device__ float g_xdbl [(long)NB*22*LQ];
__device__ float g_delta[(long)NB*192*LQ];
__device__ float g_BC   [(long)NB*LQ*16];
__device__ float g_y    [(long)NB*192*LQ];
__device__ float g_A    [192*8];
__device__ int   g_pow_ok;

// ---------------- prep: materialize A + verify power structure ----------------
__global__ void prep_kernel(const float* __restrict__ Alogs)
{
    __shared__ int ok;
    int tid = threadIdx.x;
    if (tid == 0) ok = 1;
    for (int t = tid; t < 192 * 8; t += 256) g_A[t] = -expf(Alogs[t]);
    __syncthreads();
    for (int d = tid; d < 192; d += 256) {
        float a0 = g_A[d * 8];
        for (int n = 1; n < 8; n++) {
            float expect = a0 * (float)(n + 1);
            float got = g_A[d * 8 + n];
            if (fabsf(got - expect) > 1e-5f * fabsf(expect)) atomicAnd(&ok, 0);
        }
    }
    __syncthreads();
    if (tid == 0) g_pow_ok = ok;
}

__device__ __forceinline__ float gelu_exact(float v)
{
    return 0.5f * v * (1.f + erff(v * 0.70710678118654752f));
}

// ---------------- common MMA helpers ----------------
__device__ __forceinline__ uint32_t f2tf32(float f)
{
    uint32_t o;
    asm("cvt.rna.tf32.f32 %0, %1;" : "=r"(o) : "f"(f));
    return o;
}

__device__ __forceinline__ uint32_t bits2tf32(uint32_t w)
{
    uint32_t o;
    asm("cvt.rna.tf32.f32 %0, %1;" : "=r"(o) : "f"(__uint_as_float(w)));
    return o;
}

__device__ __forceinline__ void mma_tf32(float* d, const uint32_t* a, const uint32_t* b)
{
    asm volatile("mma.sync.aligned.m16n8k8.row.col.f32.tf32.tf32.f32 "
                 "{%0,%1,%2,%3}, {%4,%5,%6,%7}, {%8,%9}, {%0,%1,%2,%3};"
                 : "+f"(d[0]), "+f"(d[1]), "+f"(d[2]), "+f"(d[3])
                 : "r"(a[0]), "r"(a[1]), "r"(a[2]), "r"(a[3]),
                   "r"(b[0]), "r"(b[1]));
}

__device__ __forceinline__ void epi_store(float* Ob, float* O2b, int n, int m, float v, int EPI)
{
    if (EPI == 1) {
        if (n < 96) O2b[(long)n * LQ + m] = gelu_exact(v);
        else        Ob [(long)n * LQ + m] = v;
    } else if (EPI == 2) {
        int tr = ((m & 63) << 6) | (m >> 6);
        Ob[(long)n * LQ + tr] = v / (1.f + __expf(-v));
    } else {
        Ob[(long)n * LQ + m] = v;
    }
}

__device__ __forceinline__ void cpa16(uint32_t dst, const float* src)
{
    asm volatile("cp.async.cg.shared.global [%0], [%1], 16;" :: "r"(dst), "l"(src));
}

// ---------------- split tf32 GEMM (R7-proven layout: sW[64][36], sA[32][136]) --------
__global__ void __launch_bounds__(256)
gemm_tf32_split_kernel(const float* __restrict__ Act, long actStride,
                       const float* __restrict__ W, const float* __restrict__ bias,
                       float* __restrict__ O, long oStride, int N, int K)
{
    extern __shared__ uint32_t dsm[];
    uint32_t* sWb = dsm;
    uint32_t* sWs = dsm + 64*36;
    uint32_t* sAb = dsm + 2*64*36;
    uint32_t* sAs = sAb + 32*136;

    const float* Ab = Act + (long)blockIdx.z * actStride;
    float* Ob = O + (long)blockIdx.z * oStride;
    int m0 = blockIdx.x * 128, n0 = blockIdx.y * 64;
    int tid = threadIdx.x, lane = tid & 31, wid = tid >> 5;
    int wn = (wid & 1) * 32;
    int wm = (wid >> 1) * 32;

    float d[2][4][4];
#pragma unroll
    for (int i = 0; i < 2; i++)
#pragma unroll
        for (int j = 0; j < 4; j++)
#pragma unroll
            for (int q = 0; q < 4; q++) d[i][j][q] = 0.f;

    for (int kc = 0; kc < K; kc += 32) {
#pragma unroll
        for (int i = 0; i < 2; i++) {
            int e = tid + i * 256;
            int row = e >> 3, c4 = (e & 7) * 4;
            int n = n0 + row;
            float4 v = make_float4(0.f, 0.f, 0.f, 0.f);
            if (n < N) v = *(const float4*)(W + (long)n * K + kc + c4);
            float vv[4] = {v.x, v.y, v.z, v.w};
#pragma unroll
            for (int t = 0; t < 4; t++) {
                uint32_t bg = f2tf32(vv[t]);
                sWb[row * 36 + c4 + t] = bg;
                sWs[row * 36 + c4 + t] = f2tf32(vv[t] - __uint_as_float(bg));
            }
        }
#pragma unroll
        for (int i = 0; i < 4; i++) {
            int e = tid + i * 256;
            int row = e >> 5, c4 = (e & 31) * 4;
            float4 v = *(const float4*)(Ab + (long)(kc + row) * LQ + m0 + c4);
            float vv[4] = {v.x, v.y, v.z, v.w};
#pragma unroll
            for (int t = 0; t < 4; t++) {
                uint32_t bg = f2tf32(vv[t]);
                sAb[row * 136 + c4 + t] = bg;
                sAs[row * 136 + c4 + t] = f2tf32(vv[t] - __uint_as_float(bg));
            }
        }
        __syncthreads();

#pragma unroll
        for (int ks = 0; ks < 4; ks++) {
            int kk = ks * 8;
            uint32_t afrB[2][4], bfrB[4][2];
            uint32_t afrS[2][4], bfrS[4][2];
            int r = wn + (lane >> 2);
            int c = kk + (lane & 3);
#pragma unroll
            for (int i = 0; i < 2; i++) {
                int rb = r + i * 16;
                afrB[i][0] = sWb[rb * 36 + c];
                afrB[i][1] = sWb[(rb + 8) * 36 + c];
                afrB[i][2] = sWb[rb * 36 + c + 4];
                afrB[i][3] = sWb[(rb + 8) * 36 + c + 4];
                afrS[i][0] = sWs[rb * 36 + c];
                afrS[i][1] = sWs[(rb + 8) * 36 + c];
                afrS[i][2] = sWs[rb * 36 + c + 4];
                afrS[i][3] = sWs[(rb + 8) * 36 + c + 4];
            }
            int mcol = wm + (lane >> 2);
            int krow = kk + (lane & 3);
#pragma unroll
            for (int j = 0; j < 4; j++) {
                bfrB[j][0] = sAb[krow * 136 + mcol + j * 8];
                bfrB[j][1] = sAb[(krow + 4) * 136 + mcol + j * 8];
                bfrS[j][0] = sAs[krow * 136 + mcol + j * 8];
                bfrS[j][1] = sAs[(krow + 4) * 136 + mcol + j * 8];
            }
#pragma unroll
            for (int i = 0; i < 2; i++)
#pragma unroll
                for (int j = 0; j < 4; j++) {
                    mma_tf32(d[i][j], afrB[i], bfrS[j]);
                    mma_tf32(d[i][j], afrS[i], bfrB[j]);
                    mma_tf32(d[i][j], afrB[i], bfrB[j]);
                }
        }
        __syncthreads();
    }

#pragma unroll
    for (int i = 0; i < 2; i++) {
        int n = n0 + wn + i * 16 + (lane >> 2);
        float bb0 = (bias && n < N) ? bias[n] : 0.f;
        float bb1 = (bias && n + 8 < N) ? bias[n + 8] : 0.f;
#pragma unroll
        for (int j = 0; j < 4; j++) {
            int m = m0 + wm + j * 8 + 2 * (lane & 3);
            if (n < N) {
                float* p0 = Ob + (long)n * LQ + m;
                p0[0] = d[i][j][0] + bb0;
                p0[1] = d[i][j][1] + bb0;
            }
            if (n + 8 < N) {
                float* p1 = Ob + (long)(n + 8) * LQ + m;
                p1[0] = d[i][j][2] + bb1;
                p1[1] = d[i][j][3] + bb1;
            }
        }
    }
}

// ---------------- plain tf32 GEMM with cp.async double-buffered pipeline --------------
#define WB_WORDS (64*36)   // 2304
#define AB_WORDS (32*136)  // 4352

template<int EPI>
__global__ void __launch_bounds__(256)
gemm_tf32_pipe_kernel(const float* __restrict__ Act, long actStride,
                      const float* __restrict__ W, const float* __restrict__ bias,
                      float* __restrict__ O, float* __restrict__ O2,
                      long oStride, int N, int K)
{
    extern __shared__ uint32_t dsm[];
    const float* Ab = Act + (long)blockIdx.z * actStride;
    float* Ob = O + (long)blockIdx.z * oStride;
    float* O2b = O2 ? (O2 + (long)blockIdx.z * oStride) : nullptr;
    int m0 = blockIdx.x * 128, n0 = blockIdx.y * 64;
    int tid = threadIdx.x, lane = tid & 31, wid = tid >> 5;
    int wn = (wid & 1) * 32;
    int wm = (wid >> 1) * 32;

    uint32_t smem_base = (uint32_t)__cvta_generic_to_shared(dsm);

    float d[2][4][4];
#pragma unroll
    for (int i = 0; i < 2; i++)
#pragma unroll
        for (int j = 0; j < 4; j++)
#pragma unroll
            for (int q = 0; q < 4; q++) d[i][j][q] = 0.f;

    int wr0 = tid >> 3, wj = (tid & 7) * 4;

    auto issue_tile = [&](int buf, int kc) {
#pragma unroll
        for (int i = 0; i < 2; i++) {
            int row = wr0 + i * 32;
            uint32_t dst = smem_base + (buf * WB_WORDS + row * 36 + wj) * 4;
            cpa16(dst, W + (long)(n0 + row) * K + kc + wj);
        }
#pragma unroll
        for (int i = 0; i < 4; i++) {
            int e = tid + i * 256;
            int kk = e >> 5, c4 = (e & 31) * 4;
            uint32_t dst = smem_base + (2 * WB_WORDS + buf * AB_WORDS + kk * 136 + c4) * 4;
            cpa16(dst, Ab + (long)(kc + kk) * LQ + m0 + c4);
        }
        asm volatile("cp.async.commit_group;" ::: "memory");
    };

    int nT = K >> 5;
    issue_tile(0, 0);
    for (int kt = 0; kt < nT; kt++) {
        int cur = kt & 1;
        if (kt + 1 < nT) {
            issue_tile(cur ^ 1, (kt + 1) << 5);
            asm volatile("cp.async.wait_group 1;" ::: "memory");
        } else {
            asm volatile("cp.async.wait_group 0;" ::: "memory");
        }
        __syncthreads();

        const uint32_t* sWc = dsm + cur * WB_WORDS;
        const uint32_t* sAc = dsm + 2 * WB_WORDS + cur * AB_WORDS;
#pragma unroll
        for (int ks = 0; ks < 4; ks++) {
            int kk = ks * 8;
            uint32_t afr[2][4], bfr[4][2];
            int r = wn + (lane >> 2);
            int c = kk + (lane & 3);
#pragma unroll
            for (int i = 0; i < 2; i++) {
                int rb = r + i * 16;
                afr[i][0] = bits2tf32(sWc[rb * 36 + c]);
                afr[i][1] = bits2tf32(sWc[(rb + 8) * 36 + c]);
                afr[i][2] = bits2tf32(sWc[rb * 36 + c + 4]);
                afr[i][3] = bits2tf32(sWc[(rb + 8) * 36 + c + 4]);
            }
            int mcol = wm + (lane >> 2);
            int krow = kk + (lane & 3);
#pragma unroll
            for (int j = 0; j < 4; j++) {
                bfr[j][0] = bits2tf32(sAc[krow * 136 + mcol + j * 8]);
                bfr[j][1] = bits2tf32(sAc[(krow + 4) * 136 + mcol + j * 8]);
            }
#pragma unroll
            for (int i = 0; i < 2; i++)
#pragma unroll
                for (int j = 0; j < 4; j++)
                    mma_tf32(d[i][j], afr[i], bfr[j]);
        }
        __syncthreads();
    }

#pragma unroll
    for (int i = 0; i < 2; i++) {
        int n = n0 + wn + i * 16 + (lane >> 2);
        float bb0 = bias ? bias[n] : 0.f;
        float bb1 = bias ? bias[n + 8] : 0.f;
#pragma unroll
        for (int j = 0; j < 4; j++) {
            int m = m0 + wm + j * 8 + 2 * (lane & 3);
            epi_store(Ob, O2b, n, m,         d[i][j][0] + bb0, EPI);
            epi_store(Ob, O2b, n, m + 1,     d[i][j][1] + bb0, EPI);
            epi_store(Ob, O2b, n + 8, m,     d[i][j][2] + bb1, EPI);
            epi_store(Ob, O2b, n + 8, m + 1, d[i][j][3] + bb1, EPI);
        }
    }
}

// ---------------- fused LN + gate + output GEMM (split tf32) --------------------------
__global__ void __launch_bounds__(256)
gemm_ln_kernel(const float* __restrict__ Y, const float* __restrict__ Z,
               const float* __restrict__ gamma, const float* __restrict__ beta,
               const float* __restrict__ W, float* __restrict__ O,
               int N, int K)
{
    extern __shared__ uint32_t dsm[];
    uint32_t* sWb = dsm;
    uint32_t* sWs = dsm + 64*36;
    uint32_t* sAb = dsm + 2*64*36;
    uint32_t* sAs = sAb + 32*136;
    float* sMu = (float*)(sAs + 32*136);       // 128
    float* sRs = sMu + 128;                    // 128
    float* sG  = sRs + 128;                    // 192
    float* sB  = sG + 192;                     // 192
    float* sRedS = sB + 192;                   // 256
    float* sRedQ = sRedS + 256;                // 256

    const float* Yb = Y + (long)blockIdx.z * 192 * LQ;
    const float* Zb = Z + (long)blockIdx.z * 192 * LQ;
    float* Ob = O + (long)blockIdx.z * 96 * LQ;
    int m0 = blockIdx.x * 128, n0 = blockIdx.y * 64;
    int tid = threadIdx.x, lane = tid & 31, wid = tid >> 5;
    int wn = (wid & 1) * 32;
    int wm = (wid >> 1) * 32;

    // phase 0: column stats over K=192 (two halves of 96 per column)
    {
        int c = tid & 127, half = tid >> 7;
        float s = 0.f, ss = 0.f;
        const float* col = Yb + (long)(half * 96) * LQ + m0 + c;
        for (int k = 0; k < 96; k++) {
            float v = col[(long)k * LQ];
            s += v; ss += v * v;
        }
        sRedS[tid] = s; sRedQ[tid] = ss;
        for (int e = tid; e < 192; e += 256) { sG[e] = gamma[e]; sB[e] = beta[e]; }
        __syncthreads();
        if (tid < 128) {
            float st = sRedS[tid] + sRedS[tid + 128];
            float qt = sRedQ[tid] + sRedQ[tid + 128];
            float mu = st * (1.f / 192.f);
            float var = qt * (1.f / 192.f) - mu * mu;
            sMu[tid] = mu;
            sRs[tid] = rsqrtf(var + 1e-5f);
        }
        __syncthreads();
    }

    float d[2][4][4];
#pragma unroll
    for (int i = 0; i < 2; i++)
#pragma unroll
        for (int j = 0; j < 4; j++)
#pragma unroll
            for (int q = 0; q < 4; q++) d[i][j][q] = 0.f;

    for (int kc = 0; kc < K; kc += 32) {
#pragma unroll
        for (int i = 0; i < 2; i++) {
            int e = tid + i * 256;
            int row = e >> 3, c4 = (e & 7) * 4;
            int n = n0 + row;
            float4 v = make_float4(0.f, 0.f, 0.f, 0.f);
            if (n < N) v = *(const float4*)(W + (long)n * K + kc + c4);
            float vv[4] = {v.x, v.y, v.z, v.w};
#pragma unroll
            for (int t = 0; t < 4; t++) {
                uint32_t bg = f2tf32(vv[t]);
                sWb[row * 36 + c4 + t] = bg;
                sWs[row * 36 + c4 + t] = f2tf32(vv[t] - __uint_as_float(bg));
            }
        }
#pragma unroll
        for (int i = 0; i < 4; i++) {
            int e = tid + i * 256;
            int row = e >> 5, c4 = (e & 31) * 4;
            int kg = kc + row;
            float4 v = *(const float4*)(Yb + (long)kg * LQ + m0 + c4);
            float4 zv = *(const float4*)(Zb + (long)kg * LQ + m0 + c4);
            float vv[4] = {v.x, v.y, v.z, v.w};
            float zz[4] = {zv.x, zv.y, zv.z, zv.w};
            float gk = sG[kg], bk = sB[kg];
#pragma unroll
            for (int t = 0; t < 4; t++) {
                int col = c4 + t;
                float yn = ((vv[t] - sMu[col]) * sRs[col] * gk + bk) * zz[t];
                uint32_t bg = f2tf32(yn);
                sAb[row * 136 + col] = bg;
                sAs[row * 136 + col] = f2tf32(yn - __uint_as_float(bg));
            }
        }
        __syncthreads();

#pragma unroll
        for (int ks = 0; ks < 4; ks++) {
            int kk = ks * 8;
            uint32_t afrB[2][4], bfrB[4][2];
            uint32_t afrS[2][4], bfrS[4][2];
            int r = wn + (lane >> 2);
            int c = kk + (lane & 3);
#pragma unroll
            for (int i = 0; i < 2; i++) {
                int rb = r + i * 16;
                afrB[i][0] = sWb[rb * 36 + c];
                afrB[i][1] = sWb[(rb + 8) * 36 + c];
                afrB[i][2] = sWb[rb * 36 + c + 4];
                afrB[i][3] = sWb[(rb + 8) * 36 + c + 4];
                afrS[i][0] = sWs[rb * 36 + c];
                afrS[i][1] = sWs[(rb + 8) * 36 + c];
                afrS[i][2] = sWs[rb * 36 + c + 4];
                afrS[i][3] = sWs[(rb + 8) * 36 + c + 4];
            }
            int mcol = wm + (lane >> 2);
            int krow = kk + (lane & 3);
#pragma unroll
            for (int j = 0; j < 4; j++) {
                bfrB[j][0] = sAb[krow * 136 + mcol + j * 8];
                bfrB[j][1] = sAb[(krow + 4) * 136 + mcol + j * 8];
                bfrS[j][0] = sAs[krow * 136 + mcol + j * 8];
                bfrS[j][1] = sAs[(krow + 4) * 136 + mcol + j * 8];
            }
#pragma unroll
            for (int i = 0; i < 2; i++)
#pragma unroll
                for (int j = 0; j < 4; j++) {
                    mma_tf32(d[i][j], afrB[i], bfrS[j]);
                    mma_tf32(d[i][j], afrS[i], bfrB[j]);
                    mma_tf32(d[i][j], afrB[i], bfrB[j]);
                }
        }
        __syncthreads();
    }

#pragma unroll
    for (int i = 0; i < 2; i++) {
        int n = n0 + wn + i * 16 + (lane >> 2);
#pragma unroll
        for (int j = 0; j < 4; j++) {
            int m = m0 + wm + j * 8 + 2 * (lane & 3);
            if (n < N) {
                float* p0 = Ob + (long)n * LQ + m;
                p0[0] = d[i][j][0];
                p0[1] = d[i][j][1];
            }
            if (n + 8 < N) {
                float* p1 = Ob + (long)(n + 8) * LQ + m;
                p1[0] = d[i][j][2];
                p1[1] = d[i][j][3];
            }
        }
    }
}

// ---------------- z branch: merged multi-scale depthwise conv + GELU ----------------
template<int KSZ>
__device__ __forceinline__ void dwconv_body(float* sm, const float* __restrict__ W,
                                            const float* __restrict__ bias,
                                            int c, int b, int co)
{
    constexpr int PAD = KSZ / 2;
    constexpr int SH = 64 + 2 * PAD;
    int tid = threadIdx.x;
    const float* src = g_t + ((long)b * 384 + co) * LQ;

    for (int e = tid; e < SH * 72; e += 256) sm[e] = 0.f;
    __syncthreads();
    for (int e = tid; e < LQ; e += 256) {
        int h = e >> 6, w = e & 63;
        sm[(h + PAD) * 72 + (w + PAD)] = src[e];
    }
    __syncthreads();

    float wreg[KSZ * KSZ];
#pragma unroll
    for (int i = 0; i < KSZ * KSZ; i++) wreg[i] = W[c * KSZ * KSZ + i];
    float bb = bias[c];

    float* dst = g_t2 + ((long)b * 384 + co) * LQ;
    for (int e = tid; e < LQ; e += 256) {
        int h = e >> 6, w = e & 63;
        float acc = bb;
#pragma unroll
        for (int ky = 0; ky < KSZ; ky++) {
            const float* row = sm + (h + ky) * 72 + w;
#pragma unroll
            for (int kx = 0; kx < KSZ; kx++)
                acc += row[kx] * wreg[ky * KSZ + kx];
        }
        dst[e] = gelu_exact(acc);
    }
}

__global__ void dwconv_all_kernel(const float* __restrict__ W3, const float* __restrict__ b3,
                                  const float* __restrict__ W5, const float* __restrict__ b5,
                                  const float* __restrict__ W7, const float* __restrict__ b7)
{
    __shared__ float sm[70 * 72];
    int cc = blockIdx.x;
    int b = blockIdx.y;
    if (cc < 96)       dwconv_body<3>(sm, W3, b3, cc,        b,  96 + cc);
    else if (cc < 192) dwconv_body<5>(sm, W5, b5, cc - 96,   b, 192 + (cc - 96));
    else               dwconv_body<7>(sm, W7, b7, cc - 192,  b, 288 + (cc - 192));
}

// ---------------- x branch: depthwise 3x3 + bias + silu ----------------
__global__ void dw3_silu_kernel(const float* __restrict__ W, const float* __restrict__ bias)
{
    __shared__ float sm[66 * 68];
    int c = blockIdx.x;
    int b = blockIdx.y;
    int tid = threadIdx.x;
    const float* src = g_xz + ((long)b * 384 + c) * LQ;
    for (int e = tid; e < 66 * 68; e += 256) sm[e] = 0.f;
    __syncthreads();
    for (int e = tid; e < LQ; e += 256) {
        int h = e >> 6, w = e & 63;
        sm[(h + 1) * 68 + (w + 1)] = src[e];
    }
    __syncthreads();
    float w0 = W[c*9+0], w1 = W[c*9+1], w2 = W[c*9+2];
    float w3 = W[c*9+3], w4 = W[c*9+4], w5 = W[c*9+5];
    float w6 = W[c*9+6], w7 = W[c*9+7], w8 = W[c*9+8];
    float bb = bias[c];
    float* dst = g_xc + ((long)b * 192 + c) * LQ;
    for (int e = tid; e < LQ; e += 256) {
        int h = e >> 6, w = e & 63;
        const float* r0 = sm + h * 68 + w;
        float acc = bb + r0[0]*w0 + r0[1]*w1 + r0[2]*w2
                       + r0[68]*w3 + r0[69]*w4 + r0[70]*w5
                       + r0[136]*w6 + r0[137]*w7 + r0[138]*w8;
        dst[e] = acc / (1.f + __expf(-acc));
    }
}

// ---------------- haar 1x1 conv + strided combine -> yL, y_mean ----------------
__global__ void haar_kernel(const float* __restrict__ Wh)
{
    extern __shared__ float smh[];
    float* sW = smh;
    float* s1 = smh + 32 * 192;
    float* s2 = s1 + 192 * 32;
    int i = blockIdx.x, b = blockIdx.y;
    int tid = threadIdx.x;
    for (int e = tid; e < 32 * 192; e += 256) sW[e] = Wh[e];
    const float* xcb = g_xc + (long)b * 192 * LQ;
    for (int e = tid; e < 192 * 32; e += 256) {
        int d = e >> 5, j = e & 31;
        const float* row0 = xcb + (long)d * LQ + (2 * i) * 64 + 2 * j;
        float xa = row0[0], xb = row0[1];
        float xc2 = row0[64], xd = row0[65];
        s1[d * 32 + j] = xa + xb + xc2 + xd;
        s2[d * 32 + j] = 3.f * xa - xb - xc2 - xd;
    }
    __syncthreads();
    for (int e = tid; e < 2048; e += 256) {
        int which = e >> 10;
        int ch = (e >> 5) & 31;
        int j = e & 31;
        const float* sv = (which ? s2 : s1) + j;
        const float* wr = sW + ch * 192;
        float acc = 0.f;
#pragma unroll 4
        for (int d = 0; d < 192; d++) acc += wr[d] * sv[d * 32];
        acc *= which ? (1.f / 6.f) : 0.5f;
        int n = ch >> 2;
        int lpos = (ch & 3) * 1024 + i * 32 + j;
        float* dst = which ? g_ym : g_yL;
        dst[((long)b * 8 + n) * LQ + lpos] = acc;
    }
}

// ---------------- fused: conv1d(k=7) + dt projection + softplus + B/C assembly --------
__global__ void convdtbc_kernel(const float* __restrict__ Wx, const float* __restrict__ bx,
                                const float* __restrict__ Wdt, const float* __restrict__ dtb)
{
    __shared__ float sIn[22][264];
    __shared__ float sWd[192 * 6];
    __shared__ float sBd[192];
    __shared__ float sWc[22 * 7];
    __shared__ float sbc[22];
    int tid = threadIdx.x;
    int l0 = blockIdx.x * 256;
    int b = blockIdx.y;

    for (int e = tid; e < 1152; e += 256) sWd[e] = Wdt[e];
    for (int e = tid; e < 192; e += 256) sBd[e] = dtb[e];
    for (int e = tid; e < 154; e += 256) sWc[e] = Wx[e];
    for (int e = tid; e < 22; e += 256) sbc[e] = bx[e];
    for (int e = tid; e < 22 * 262; e += 256) {
        int c = e / 262, p = e % 262;
        int l = l0 + p - 3;
        float v = 0.f;
        if ((unsigned)l < (unsigned)LQ) v = g_xdbl[((long)b * 22 + c) * LQ + l];
        sIn[c][p] = v;
    }
    __syncthreads();

    int l = l0 + tid;
    float r[22];
#pragma unroll
    for (int c = 0; c < 22; c++) {
        float acc = sbc[c];
#pragma unroll
        for (int k = 0; k < 7; k++) acc += sIn[c][tid + k] * sWc[c * 7 + k];
        r[c] = acc;
    }
    float* dout = g_delta + (long)b * 192 * LQ + l;
    for (int d = 0; d < 192; d++) {
        float s = sBd[d];
#pragma unroll
        for (int rr = 0; rr < 6; rr++) s += sWd[d * 6 + rr] * r[rr];
        float sp = (s > 20.f) ? s : log1pf(expf(s));
        dout[(long)d * LQ] = sp;
    }
    float* o = g_BC + ((long)b * LQ + l) * 16;
    float bs[8], cs[8];
#pragma unroll
    for (int n = 0; n < 8; n++) {
        bs[n] = r[6 + n]  * g_yL[((long)b * 8 + n) * LQ + l] + 1e-6f;
        cs[n] = r[14 + n] * g_ym[((long)b * 8 + n) * LQ + l] + 1e-6f;
    }
    ((float4*)o)[0] = make_float4(bs[0], bs[1], bs[2], bs[3]);
    ((float4*)o)[1] = make_float4(bs[4], bs[5], bs[6], bs[7]);
    ((float4*)o)[2] = make_float4(cs[0], cs[1], cs[2], cs[3]);
    ((float4*)o)[3] = make_float4(cs[4], cs[5], cs[6], cs[7]);
}

// ---------------- selective scan (512 threads, 8 l per thread) ----------------
// smem: delta 4096 + u 4096 + scan 2*8*512 = 16384 floats = 65536 bytes
#define SCAN_SMEM 65536

__device__ __forceinline__ void make_powers(float q, float* p)
{
    float q2 = q * q;
    float q4 = q2 * q2;
    p[0] = q;       p[1] = q2;      p[2] = q2 * q;  p[3] = q4;
    p[4] = q4 * q;  p[5] = q4 * q2; p[6] = p[5] * q; p[7] = q4 * q4;
}

__global__ void scan_kernel(const float* __restrict__ Ds)
{
    extern __shared__ float sm[];
    float* sDelta = sm;
    float* sU = sm + 4096;
    float* sScan = sm + 8192;          // [8][512] A | [8][512] B
    int bd = blockIdx.x;
    int b = bd / 192, d = bd % 192;
    int tid = threadIdx.x;             // 512
    const float* dp = g_delta + ((long)b * 192 + d) * LQ;
    const float* up = g_xc    + ((long)b * 192 + d) * LQ;
    for (int e = tid; e < LQ; e += 512) { sDelta[e] = dp[e]; sU[e] = up[e]; }
    float An[8];
#pragma unroll
    for (int n = 0; n < 8; n++) An[n] = g_A[d * 8 + n];
    bool powok = (g_pow_ok != 0);
    __syncthreads();
    const float* bc = g_BC + (long)b * LQ * 16;

    float a[8], hh[8];
#pragma unroll
    for (int n = 0; n < 8; n++) { a[n] = 1.f; hh[n] = 0.f; }
    int base = tid * 8;
#pragma unroll
    for (int i = 0; i < 8; i++) {
        int l = base + i;
        float delta = sDelta[l];
        float du = delta * sU[l];
        const float4* bc4 = (const float4*)(bc + (long)l * 16);
        float4 b0 = bc4[0], b1 = bc4[1];
        float bl[8] = {b0.x,b0.y,b0.z,b0.w,b1.x,b1.y,b1.z,b1.w};
        float p[8];
        if (powok) {
            make_powers(__expf(delta * An[0]), p);
        } else {
#pragma unroll
            for (int n = 0; n < 8; n++) p[n] = __expf(delta * An[n]);
        }
#pragma unroll
        for (int n = 0; n < 8; n++) {
            hh[n] = p[n] * hh[n] + du * bl[n];
            a[n] *= p[n];
        }
    }
#pragma unroll
    for (int n = 0; n < 8; n++) { sScan[n * 512 + tid] = a[n]; sScan[4096 + n * 512 + tid] = hh[n]; }
    __syncthreads();

    for (int off = 1; off < 512; off <<= 1) {
        float pa[8], pb[8];
        if (tid >= off) {
#pragma unroll
            for (int n = 0; n < 8; n++) {
                pa[n] = sScan[n * 512 + tid - off];
                pb[n] = sScan[4096 + n * 512 + tid - off];
            }
        }
        __syncthreads();
        if (tid >= off) {
#pragma unroll
            for (int n = 0; n < 8; n++) {
                float a2 = sScan[n * 512 + tid];
                float b2 = sScan[4096 + n * 512 + tid];
                sScan[n * 512 + tid] = pa[n] * a2;
                sScan[4096 + n * 512 + tid] = a2 * pb[n] + b2;
            }
        }
        __syncthreads();
    }
    float h0[8];
#pragma unroll
    for (int n = 0; n < 8; n++) h0[n] = (tid == 0) ? 0.f : sScan[4096 + n * 512 + tid - 1];
    __syncthreads();

    float Dd = Ds[d];
#pragma unroll
    for (int i = 0; i < 8; i++) {
        int l = base + i;
        float delta = sDelta[l];
        float u = sU[l];
        float du = delta * u;
        const float4* bc4 = (const float4*)(bc + (long)l * 16);
        float4 b0 = bc4[0], b1 = bc4[1], c0 = bc4[2], c1 = bc4[3];
        float bl[8] = {b0.x,b0.y,b0.z,b0.w,b1.x,b1.y,b1.z,b1.w};
        float cl[8] = {c0.x,c0.y,c0.z,c0.w,c1.x,c1.y,c1.z,c1.w};
        float p[8];
        if (powok) {
            make_powers(__expf(delta * An[0]), p);
        } else {
#pragma unroll
            for (int n = 0; n < 8; n++) p[n] = __expf(delta * An[n]);
        }
        float y = Dd * u;
#pragma unroll
        for (int n = 0; n < 8; n++) {
            h0[n] = p[n] * h0[n] + du * bl[n];
            y += h0[n] * cl[n];
        }
        sScan[l] = y;
    }
    __syncthreads();
    float* yo = g_y + ((long)b * 192 + d) * LQ;
    for (int e = tid; e < LQ; e += 512) yo[e] = sScan[e];
}

// ---------------- host launcher ----------------
extern "C" void kernel_launch(void* const* d_in, const int* in_sizes, int n_in,
                              void* d_out, int out_size)
{
    const float* x        = (const float*)d_in[0];
    const float* W_in     = (const float*)d_in[1];
    const float* W_dwc_i  = (const float*)d_in[2];
    const float* b_dwc_i  = (const float*)d_in[3];
    const float* W_dw3    = (const float*)d_in[4];
    const float* b_dw3    = (const float*)d_in[5];
    const float* W_dw5    = (const float*)d_in[6];
    const float* b_dw5    = (const float*)d_in[7];
    const float* W_dw7    = (const float*)d_in[8];
    const float* b_dw7    = (const float*)d_in[9];
    const float* W_dwc_f  = (const float*)d_in[10];
    const float* b_dwc_f  = (const float*)d_in[11];
    const float* W_conv2d = (const float*)d_in[12];
    const float* b_conv2d = (const float*)d_in[13];
    const float* W_haar   = (const float*)d_in[14];
    const float* x_proj_w = (const float*)d_in[15];
    const float* W_xconv  = (const float*)d_in[16];
    const float* b_xconv  = (const float*)d_in[17];
    const float* dt_w     = (const float*)d_in[18];
    const float* dt_b     = (const float*)d_in[19];
    const float* A_logs   = (const float*)d_in[20];
    const float* Ds       = (const float*)d_in[21];
    const float* ln_g     = (const float*)d_in[22];
    const float* ln_b     = (const float*)d_in[23];
    const float* W_out    = (const float*)d_in[24];
    float* out = (float*)d_out;

    float *p_xz, *p_t, *p_t2, *p_zsil, *p_xc, *p_xdbl, *p_y;
    cudaGetSymbolAddress((void**)&p_xz, g_xz);
    cudaGetSymbolAddress((void**)&p_t, g_t);
    cudaGetSymbolAddress((void**)&p_t2, g_t2);
    cudaGetSymbolAddress((void**)&p_zsil, g_zsil);
    cudaGetSymbolAddress((void**)&p_xc, g_xc);
    cudaGetSymbolAddress((void**)&p_xdbl, g_xdbl);
    cudaGetSymbolAddress((void**)&p_y, g_y);

    const int SMEM_SPLIT = (2*64*36 + 2*32*136) * 4;      // 53248
    const int SMEM_PIPE  = (2*WB_WORDS + 2*AB_WORDS) * 4; // 53248
    const int SMEM_LN    = SMEM_SPLIT + (128+128+192+192+256+256) * 4; // 57856
    cudaFuncSetAttribute((const void*)gemm_tf32_split_kernel,
                         cudaFuncAttributeMaxDynamicSharedMemorySize, SMEM_SPLIT);
    cudaFuncSetAttribute((const void*)gemm_tf32_pipe_kernel<1>,
                         cudaFuncAttributeMaxDynamicSharedMemorySize, SMEM_PIPE);
    cudaFuncSetAttribute((const void*)gemm_tf32_pipe_kernel<2>,
                         cudaFuncAttributeMaxDynamicSharedMemorySize, SMEM_PIPE);
    cudaFuncSetAttribute((const void*)gemm_ln_kernel,
                         cudaFuncAttributeMaxDynamicSharedMemorySize, SMEM_LN);
    cudaFuncSetAttribute(haar_kernel, cudaFuncAttributeMaxDynamicSharedMemorySize, 73728);
    cudaFuncSetAttribute(scan_kernel, cudaFuncAttributeMaxDynamicSharedMemorySize, SCAN_SMEM);

    static cudaStream_t sZ = nullptr;
    static cudaEvent_t evFork = nullptr, evJoin = nullptr;
    if (!sZ) {
        cudaStreamCreateWithFlags(&sZ, cudaStreamNonBlocking);
        cudaEventCreateWithFlags(&evFork, cudaEventDisableTiming);
        cudaEventCreateWithFlags(&evJoin, cudaEventDisableTiming);
    }

    prep_kernel<<<1, 256>>>(A_logs);

    // K1: input GEMM (split tf32, ~fp32 accuracy)
    gemm_tf32_split_kernel<<<dim3(32, 6, NB), 256, SMEM_SPLIT>>>(
        x, 96L * LQ, W_in, nullptr, p_xz, 384L * LQ, 384, 96);

    // ---- fork: z branch on stream sZ ----
    cudaEventRecord(evFork, 0);
    cudaStreamWaitEvent(sZ, evFork, 0);

    gemm_tf32_pipe_kernel<1><<<dim3(32, 6, NB), 256, SMEM_PIPE, sZ>>>(
        p_xz + 192L * LQ, 384L * LQ, W_dwc_i, b_dwc_i, p_t, p_t2, 384L * LQ, 384, 192);
    dwconv_all_kernel<<<dim3(288, NB), 256, 0, sZ>>>(W_dw3, b_dw3, W_dw5, b_dw5, W_dw7, b_dw7);
    gemm_tf32_pipe_kernel<2><<<dim3(32, 3, NB), 256, SMEM_PIPE, sZ>>>(
        p_t2, 384L * LQ, W_dwc_f, b_dwc_f, p_zsil, nullptr, 192L * LQ, 192, 384);
    cudaEventRecord(evJoin, sZ);

    // ---- x branch on default stream ----
    dw3_silu_kernel<<<dim3(192, NB), 256>>>(W_conv2d, b_conv2d);
    haar_kernel<<<dim3(32, NB), 256, 73728>>>(W_haar);
    gemm_tf32_split_kernel<<<dim3(32, 1, NB), 256, SMEM_SPLIT>>>(
        p_xc, 192L * LQ, x_proj_w, nullptr, p_xdbl, 22L * LQ, 22, 192);
    convdtbc_kernel<<<dim3(16, NB), 256>>>(W_xconv, b_xconv, dt_w, dt_b);
    scan_kernel<<<NB * 192, 512, SCAN_SMEM>>>(Ds);

    // ---- join, then fused LN+gate+output GEMM ----
    cudaStreamWaitEvent(0, evJoin, 0);
    gemm_ln_kernel<<<dim3(32, 2, NB), 256, SMEM_LN>>>(
        p_y, p_zsil, ln_g, ln_b, W_out, out, 96, 192);
    (void)in_sizes; (void)n_in; (void)out_size;
}

// round 14
// speedup vs baseline: 1.4659x; 1.0715x over previous
#include <cuda_runtime.h>
#include <cuda_bf16.h>
#include <stdint.h>
#include <math.h>

#define NB 8
#define LQ 4096

// ---------------- device scratch (zero-init BSS, no allocation) ----------------
__device__ float g_xz   [(long)NB*384*LQ];
__device__ float g_t    [(long)NB*384*LQ];
__device__ float g_t2   [(long)NB*384*LQ];
__device__ float g_zsil [(long)NB*192*LQ];
__device__ float g_xc   [(long)NB*192*LQ];
__device__ float g_yL   [(long)NB*8*LQ];
__device__ float g_ym   [(long)NB*8*LQ];
__device__ float g_xdbl [(long)NB*22*LQ];
__device__ float g_rsm  [(long)NB*6*LQ];    // conv1d output channels 0..5 (dt-rank)
__device__ float g_BC   [(long)NB*LQ*16];
__device__ float g_y    [(long)NB*192*LQ];
__device__ float g_A    [192*8];
__device__ int   g_pow_ok;

// ---------------- prep: materialize A + verify power structure ----------------
__global__ void prep_kernel(const float* __restrict__ Alogs)
{
    __shared__ int ok;
    int tid = threadIdx.x;
    if (tid == 0) ok = 1;
    for (int t = tid; t < 192 * 8; t += 256) g_A[t] = -expf(Alogs[t]);
    __syncthreads();
    for (int d = tid; d < 192; d += 256) {
        float a0 = g_A[d * 8];
        for (int n = 1; n < 8; n++) {
            float expect = a0 * (float)(n + 1);
            float got = g_A[d * 8 + n];
            if (fabsf(got - expect) > 1e-5f * fabsf(expect)) atomicAnd(&ok, 0);
        }
    }
    __syncthreads();
    if (tid == 0) g_pow_ok = ok;
}

__device__ __forceinline__ float gelu_exact(float v)
{
    return 0.5f * v * (1.f + erff(v * 0.70710678118654752f));
}

// ---------------- common MMA helpers ----------------
__device__ __forceinline__ uint32_t f2tf32(float f)
{
    uint32_t o;
    asm("cvt.rna.tf32.f32 %0, %1;" : "=r"(o) : "f"(f));
    return o;
}

__device__ __forceinline__ uint32_t bits2tf32(uint32_t w)
{
    uint32_t o;
    asm("cvt.rna.tf32.f32 %0, %1;" : "=r"(o) : "f"(__uint_as_float(w)));
    return o;
}

__device__ __forceinline__ void mma_tf32(float* d, const uint32_t* a, const uint32_t* b)
{
    asm volatile("mma.sync.aligned.m16n8k8.row.col.f32.tf32.tf32.f32 "
                 "{%0,%1,%2,%3}, {%4,%5,%6,%7}, {%8,%9}, {%0,%1,%2,%3};"
                 : "+f"(d[0]), "+f"(d[1]), "+f"(d[2]), "+f"(d[3])
                 : "r"(a[0]), "r"(a[1]), "r"(a[2]), "r"(a[3]),
                   "r"(b[0]), "r"(b[1]));
}

__device__ __forceinline__ void epi_store(float* Ob, float* O2b, int n, int m, float v, int EPI)
{
    if (EPI == 1) {
        if (n < 96) O2b[(long)n * LQ + m] = gelu_exact(v);
        else        Ob [(long)n * LQ + m] = v;
    } else if (EPI == 2) {
        int tr = ((m & 63) << 6) | (m >> 6);
        Ob[(long)n * LQ + tr] = v / (1.f + __expf(-v));
    } else {
        Ob[(long)n * LQ + m] = v;
    }
}

__device__ __forceinline__ void cpa16(uint32_t dst, const float* src)
{
    asm volatile("cp.async.cg.shared.global [%0], [%1], 16;" :: "r"(dst), "l"(src));
}

// ---------------- split tf32 GEMM (R7-proven layout: sW[64][36], sA[32][136]) --------
__global__ void __launch_bounds__(256)
gemm_tf32_split_kernel(const float* __restrict__ Act, long actStride,
                       const float* __restrict__ W, const float* __restrict__ bias,
                       float* __restrict__ O, long oStride, int N, int K)
{
    extern __shared__ uint32_t dsm[];
    uint32_t* sWb = dsm;
    uint32_t* sWs = dsm + 64*36;
    uint32_t* sAb = dsm + 2*64*36;
    uint32_t* sAs = sAb + 32*136;

    const float* Ab = Act + (long)blockIdx.z * actStride;
    float* Ob = O + (long)blockIdx.z * oStride;
    int m0 = blockIdx.x * 128, n0 = blockIdx.y * 64;
    int tid = threadIdx.x, lane = tid & 31, wid = tid >> 5;
    int wn = (wid & 1) * 32;
    int wm = (wid >> 1) * 32;

    float d[2][4][4];
#pragma unroll
    for (int i = 0; i < 2; i++)
#pragma unroll
        for (int j = 0; j < 4; j++)
#pragma unroll
            for (int q = 0; q < 4; q++) d[i][j][q] = 0.f;

    for (int kc = 0; kc < K; kc += 32) {
#pragma unroll
        for (int i = 0; i < 2; i++) {
            int e = tid + i * 256;
            int row = e >> 3, c4 = (e & 7) * 4;
            int n = n0 + row;
            float4 v = make_float4(0.f, 0.f, 0.f, 0.f);
            if (n < N) v = *(const float4*)(W + (long)n * K + kc + c4);
            float vv[4] = {v.x, v.y, v.z, v.w};
#pragma unroll
            for (int t = 0; t < 4; t++) {
                uint32_t bg = f2tf32(vv[t]);
                sWb[row * 36 + c4 + t] = bg;
                sWs[row * 36 + c4 + t] = f2tf32(vv[t] - __uint_as_float(bg));
            }
        }
#pragma unroll
        for (int i = 0; i < 4; i++) {
            int e = tid + i * 256;
            int row = e >> 5, c4 = (e & 31) * 4;
            float4 v = *(const float4*)(Ab + (long)(kc + row) * LQ + m0 + c4);
            float vv[4] = {v.x, v.y, v.z, v.w};
#pragma unroll
            for (int t = 0; t < 4; t++) {
                uint32_t bg = f2tf32(vv[t]);
                sAb[row * 136 + c4 + t] = bg;
                sAs[row * 136 + c4 + t] = f2tf32(vv[t] - __uint_as_float(bg));
            }
        }
        __syncthreads();

#pragma unroll
        for (int ks = 0; ks < 4; ks++) {
            int kk = ks * 8;
            uint32_t afrB[2][4], bfrB[4][2];
            uint32_t afrS[2][4], bfrS[4][2];
            int r = wn + (lane >> 2);
            int c = kk + (lane & 3);
#pragma unroll
            for (int i = 0; i < 2; i++) {
                int rb = r + i * 16;
                afrB[i][0] = sWb[rb * 36 + c];
                afrB[i][1] = sWb[(rb + 8) * 36 + c];
                afrB[i][2] = sWb[rb * 36 + c + 4];
                afrB[i][3] = sWb[(rb + 8) * 36 + c + 4];
                afrS[i][0] = sWs[rb * 36 + c];
                afrS[i][1] = sWs[(rb + 8) * 36 + c];
                afrS[i][2] = sWs[rb * 36 + c + 4];
                afrS[i][3] = sWs[(rb + 8) * 36 + c + 4];
            }
            int mcol = wm + (lane >> 2);
            int krow = kk + (lane & 3);
#pragma unroll
            for (int j = 0; j < 4; j++) {
                bfrB[j][0] = sAb[krow * 136 + mcol + j * 8];
                bfrB[j][1] = sAb[(krow + 4) * 136 + mcol + j * 8];
                bfrS[j][0] = sAs[krow * 136 + mcol + j * 8];
                bfrS[j][1] = sAs[(krow + 4) * 136 + mcol + j * 8];
            }
#pragma unroll
            for (int i = 0; i < 2; i++)
#pragma unroll
                for (int j = 0; j < 4; j++) {
                    mma_tf32(d[i][j], afrB[i], bfrS[j]);
                    mma_tf32(d[i][j], afrS[i], bfrB[j]);
                    mma_tf32(d[i][j], afrB[i], bfrB[j]);
                }
        }
        __syncthreads();
    }

#pragma unroll
    for (int i = 0; i < 2; i++) {
        int n = n0 + wn + i * 16 + (lane >> 2);
        float bb0 = (bias && n < N) ? bias[n] : 0.f;
        float bb1 = (bias && n + 8 < N) ? bias[n + 8] : 0.f;
#pragma unroll
        for (int j = 0; j < 4; j++) {
            int m = m0 + wm + j * 8 + 2 * (lane & 3);
            if (n < N) {
                float* p0 = Ob + (long)n * LQ + m;
                p0[0] = d[i][j][0] + bb0;
                p0[1] = d[i][j][1] + bb0;
            }
            if (n + 8 < N) {
                float* p1 = Ob + (long)(n + 8) * LQ + m;
                p1[0] = d[i][j][2] + bb1;
                p1[1] = d[i][j][3] + bb1;
            }
        }
    }
}

// ---------------- plain tf32 GEMM with cp.async double-buffered pipeline --------------
#define WB_WORDS (64*36)   // 2304
#define AB_WORDS (32*136)  // 4352

template<int EPI>
__global__ void __launch_bounds__(256)
gemm_tf32_pipe_kernel(const float* __restrict__ Act, long actStride,
                      const float* __restrict__ W, const float* __restrict__ bias,
                      float* __restrict__ O, float* __restrict__ O2,
                      long oStride, int N, int K)
{
    extern __shared__ uint32_t dsm[];
    const float* Ab = Act + (long)blockIdx.z * actStride;
    float* Ob = O + (long)blockIdx.z * oStride;
    float* O2b = O2 ? (O2 + (long)blockIdx.z * oStride) : nullptr;
    int m0 = blockIdx.x * 128, n0 = blockIdx.y * 64;
    int tid = threadIdx.x, lane = tid & 31, wid = tid >> 5;
    int wn = (wid & 1) * 32;
    int wm = (wid >> 1) * 32;

    uint32_t smem_base = (uint32_t)__cvta_generic_to_shared(dsm);

    float d[2][4][4];
#pragma unroll
    for (int i = 0; i < 2; i++)
#pragma unroll
        for (int j = 0; j < 4; j++)
#pragma unroll
            for (int q = 0; q < 4; q++) d[i][j][q] = 0.f;

    int wr0 = tid >> 3, wj = (tid & 7) * 4;

    auto issue_tile = [&](int buf, int kc) {
#pragma unroll
        for (int i = 0; i < 2; i++) {
            int row = wr0 + i * 32;
            uint32_t dst = smem_base + (buf * WB_WORDS + row * 36 + wj) * 4;
            cpa16(dst, W + (long)(n0 + row) * K + kc + wj);
        }
#pragma unroll
        for (int i = 0; i < 4; i++) {
            int e = tid + i * 256;
            int kk = e >> 5, c4 = (e & 31) * 4;
            uint32_t dst = smem_base + (2 * WB_WORDS + buf * AB_WORDS + kk * 136 + c4) * 4;
            cpa16(dst, Ab + (long)(kc + kk) * LQ + m0 + c4);
        }
        asm volatile("cp.async.commit_group;" ::: "memory");
    };

    int nT = K >> 5;
    issue_tile(0, 0);
    for (int kt = 0; kt < nT; kt++) {
        int cur = kt & 1;
        if (kt + 1 < nT) {
            issue_tile(cur ^ 1, (kt + 1) << 5);
            asm volatile("cp.async.wait_group 1;" ::: "memory");
        } else {
            asm volatile("cp.async.wait_group 0;" ::: "memory");
        }
        __syncthreads();

        const uint32_t* sWc = dsm + cur * WB_WORDS;
        const uint32_t* sAc = dsm + 2 * WB_WORDS + cur * AB_WORDS;
#pragma unroll
        for (int ks = 0; ks < 4; ks++) {
            int kk = ks * 8;
            uint32_t afr[2][4], bfr[4][2];
            int r = wn + (lane >> 2);
            int c = kk + (lane & 3);
#pragma unroll
            for (int i = 0; i < 2; i++) {
                int rb = r + i * 16;
                afr[i][0] = bits2tf32(sWc[rb * 36 + c]);
                afr[i][1] = bits2tf32(sWc[(rb + 8) * 36 + c]);
                afr[i][2] = bits2tf32(sWc[rb * 36 + c + 4]);
                afr[i][3] = bits2tf32(sWc[(rb + 8) * 36 + c + 4]);
            }
            int mcol = wm + (lane >> 2);
            int krow = kk + (lane & 3);
#pragma unroll
            for (int j = 0; j < 4; j++) {
                bfr[j][0] = bits2tf32(sAc[krow * 136 + mcol + j * 8]);
                bfr[j][1] = bits2tf32(sAc[(krow + 4) * 136 + mcol + j * 8]);
            }
#pragma unroll
            for (int i = 0; i < 2; i++)
#pragma unroll
                for (int j = 0; j < 4; j++)
                    mma_tf32(d[i][j], afr[i], bfr[j]);
        }
        __syncthreads();
    }

#pragma unroll
    for (int i = 0; i < 2; i++) {
        int n = n0 + wn + i * 16 + (lane >> 2);
        float bb0 = bias ? bias[n] : 0.f;
        float bb1 = bias ? bias[n + 8] : 0.f;
#pragma unroll
        for (int j = 0; j < 4; j++) {
            int m = m0 + wm + j * 8 + 2 * (lane & 3);
            epi_store(Ob, O2b, n, m,         d[i][j][0] + bb0, EPI);
            epi_store(Ob, O2b, n, m + 1,     d[i][j][1] + bb0, EPI);
            epi_store(Ob, O2b, n + 8, m,     d[i][j][2] + bb1, EPI);
            epi_store(Ob, O2b, n + 8, m + 1, d[i][j][3] + bb1, EPI);
        }
    }
}

// ---------------- fused LN + gate + output GEMM (split tf32) --------------------------
__global__ void __launch_bounds__(256)
gemm_ln_kernel(const float* __restrict__ Y, const float* __restrict__ Z,
               const float* __restrict__ gamma, const float* __restrict__ beta,
               const float* __restrict__ W, float* __restrict__ O,
               int N, int K)
{
    extern __shared__ uint32_t dsm[];
    uint32_t* sWb = dsm;
    uint32_t* sWs = dsm + 64*36;
    uint32_t* sAb = dsm + 2*64*36;
    uint32_t* sAs = sAb + 32*136;
    float* sMu = (float*)(sAs + 32*136);
    float* sRs = sMu + 128;
    float* sG  = sRs + 128;
    float* sB  = sG + 192;
    float* sRedS = sB + 192;
    float* sRedQ = sRedS + 256;

    const float* Yb = Y + (long)blockIdx.z * 192 * LQ;
    const float* Zb = Z + (long)blockIdx.z * 192 * LQ;
    float* Ob = O + (long)blockIdx.z * 96 * LQ;
    int m0 = blockIdx.x * 128, n0 = blockIdx.y * 64;
    int tid = threadIdx.x, lane = tid & 31, wid = tid >> 5;
    int wn = (wid & 1) * 32;
    int wm = (wid >> 1) * 32;

    {
        int c = tid & 127, half = tid >> 7;
        float s = 0.f, ss = 0.f;
        const float* col = Yb + (long)(half * 96) * LQ + m0 + c;
        for (int k = 0; k < 96; k++) {
            float v = col[(long)k * LQ];
            s += v; ss += v * v;
        }
        sRedS[tid] = s; sRedQ[tid] = ss;
        for (int e = tid; e < 192; e += 256) { sG[e] = gamma[e]; sB[e] = beta[e]; }
        __syncthreads();
        if (tid < 128) {
            float st = sRedS[tid] + sRedS[tid + 128];
            float qt = sRedQ[tid] + sRedQ[tid + 128];
            float mu = st * (1.f / 192.f);
            float var = qt * (1.f / 192.f) - mu * mu;
            sMu[tid] = mu;
            sRs[tid] = rsqrtf(var + 1e-5f);
        }
        __syncthreads();
    }

    float d[2][4][4];
#pragma unroll
    for (int i = 0; i < 2; i++)
#pragma unroll
        for (int j = 0; j < 4; j++)
#pragma unroll
            for (int q = 0; q < 4; q++) d[i][j][q] = 0.f;

    for (int kc = 0; kc < K; kc += 32) {
#pragma unroll
        for (int i = 0; i < 2; i++) {
            int e = tid + i * 256;
            int row = e >> 3, c4 = (e & 7) * 4;
            int n = n0 + row;
            float4 v = make_float4(0.f, 0.f, 0.f, 0.f);
            if (n < N) v = *(const float4*)(W + (long)n * K + kc + c4);
            float vv[4] = {v.x, v.y, v.z, v.w};
#pragma unroll
            for (int t = 0; t < 4; t++) {
                uint32_t bg = f2tf32(vv[t]);
                sWb[row * 36 + c4 + t] = bg;
                sWs[row * 36 + c4 + t] = f2tf32(vv[t] - __uint_as_float(bg));
            }
        }
#pragma unroll
        for (int i = 0; i < 4; i++) {
            int e = tid + i * 256;
            int row = e >> 5, c4 = (e & 31) * 4;
            int kg = kc + row;
            float4 v = *(const float4*)(Yb + (long)kg * LQ + m0 + c4);
            float4 zv = *(const float4*)(Zb + (long)kg * LQ + m0 + c4);
            float vv[4] = {v.x, v.y, v.z, v.w};
            float zz[4] = {zv.x, zv.y, zv.z, zv.w};
            float gk = sG[kg], bk = sB[kg];
#pragma unroll
            for (int t = 0; t < 4; t++) {
                int col = c4 + t;
                float yn = ((vv[t] - sMu[col]) * sRs[col] * gk + bk) * zz[t];
                uint32_t bg = f2tf32(yn);
                sAb[row * 136 + col] = bg;
                sAs[row * 136 + col] = f2tf32(yn - __uint_as_float(bg));
            }
        }
        __syncthreads();

#pragma unroll
        for (int ks = 0; ks < 4; ks++) {
            int kk = ks * 8;
            uint32_t afrB[2][4], bfrB[4][2];
            uint32_t afrS[2][4], bfrS[4][2];
            int r = wn + (lane >> 2);
            int c = kk + (lane & 3);
#pragma unroll
            for (int i = 0; i < 2; i++) {
                int rb = r + i * 16;
                afrB[i][0] = sWb[rb * 36 + c];
                afrB[i][1] = sWb[(rb + 8) * 36 + c];
                afrB[i][2] = sWb[rb * 36 + c + 4];
                afrB[i][3] = sWb[(rb + 8) * 36 + c + 4];
                afrS[i][0] = sWs[rb * 36 + c];
                afrS[i][1] = sWs[(rb + 8) * 36 + c];
                afrS[i][2] = sWs[rb * 36 + c + 4];
                afrS[i][3] = sWs[(rb + 8) * 36 + c + 4];
            }
            int mcol = wm + (lane >> 2);
            int krow = kk + (lane & 3);
#pragma unroll
            for (int j = 0; j < 4; j++) {
                bfrB[j][0] = sAb[krow * 136 + mcol + j * 8];
                bfrB[j][1] = sAb[(krow + 4) * 136 + mcol + j * 8];
                bfrS[j][0] = sAs[krow * 136 + mcol + j * 8];
                bfrS[j][1] = sAs[(krow + 4) * 136 + mcol + j * 8];
            }
#pragma unroll
            for (int i = 0; i < 2; i++)
#pragma unroll
                for (int j = 0; j < 4; j++) {
                    mma_tf32(d[i][j], afrB[i], bfrS[j]);
                    mma_tf32(d[i][j], afrS[i], bfrB[j]);
                    mma_tf32(d[i][j], afrB[i], bfrB[j]);
                }
        }
        __syncthreads();
    }

#pragma unroll
    for (int i = 0; i < 2; i++) {
        int n = n0 + wn + i * 16 + (lane >> 2);
#pragma unroll
        for (int j = 0; j < 4; j++) {
            int m = m0 + wm + j * 8 + 2 * (lane & 3);
            if (n < N) {
                float* p0 = Ob + (long)n * LQ + m;
                p0[0] = d[i][j][0];
                p0[1] = d[i][j][1];
            }
            if (n + 8 < N) {
                float* p1 = Ob + (long)(n + 8) * LQ + m;
                p1[0] = d[i][j][2];
                p1[1] = d[i][j][3];
            }
        }
    }
}

// ---------------- z branch: merged multi-scale depthwise conv + GELU ----------------
template<int KSZ>
__device__ __forceinline__ void dwconv_body(float* sm, const float* __restrict__ W,
                                            const float* __restrict__ bias,
                                            int c, int b, int co)
{
    constexpr int PAD = KSZ / 2;
    constexpr int SH = 64 + 2 * PAD;
    int tid = threadIdx.x;
    const float* src = g_t + ((long)b * 384 + co) * LQ;

    for (int e = tid; e < SH * 72; e += 256) sm[e] = 0.f;
    __syncthreads();
    for (int e = tid; e < LQ; e += 256) {
        int h = e >> 6, w = e & 63;
        sm[(h + PAD) * 72 + (w + PAD)] = src[e];
    }
    __syncthreads();

    float wreg[KSZ * KSZ];
#pragma unroll
    for (int i = 0; i < KSZ * KSZ; i++) wreg[i] = W[c * KSZ * KSZ + i];
    float bb = bias[c];

    float* dst = g_t2 + ((long)b * 384 + co) * LQ;
    for (int e = tid; e < LQ; e += 256) {
        int h = e >> 6, w = e & 63;
        float acc = bb;
#pragma unroll
        for (int ky = 0; ky < KSZ; ky++) {
            const float* row = sm + (h + ky) * 72 + w;
#pragma unroll
            for (int kx = 0; kx < KSZ; kx++)
                acc += row[kx] * wreg[ky * KSZ + kx];
        }
        dst[e] = gelu_exact(acc);
    }
}

__global__ void dwconv_all_kernel(const float* __restrict__ W3, const float* __restrict__ b3,
                                  const float* __restrict__ W5, const float* __restrict__ b5,
                                  const float* __restrict__ W7, const float* __restrict__ b7)
{
    __shared__ float sm[70 * 72];
    int cc = blockIdx.x;
    int b = blockIdx.y;
    if (cc < 96)       dwconv_body<3>(sm, W3, b3, cc,        b,  96 + cc);
    else if (cc < 192) dwconv_body<5>(sm, W5, b5, cc - 96,   b, 192 + (cc - 96));
    else               dwconv_body<7>(sm, W7, b7, cc - 192,  b, 288 + (cc - 192));
}

// ---------------- x branch: depthwise 3x3 + bias + silu ----------------
__global__ void dw3_silu_kernel(const float* __restrict__ W, const float* __restrict__ bias)
{
    __shared__ float sm[66 * 68];
    int c = blockIdx.x;
    int b = blockIdx.y;
    int tid = threadIdx.x;
    const float* src = g_xz + ((long)b * 384 + c) * LQ;
    for (int e = tid; e < 66 * 68; e += 256) sm[e] = 0.f;
    __syncthreads();
    for (int e = tid; e < LQ; e += 256) {
        int h = e >> 6, w = e & 63;
        sm[(h + 1) * 68 + (w + 1)] = src[e];
    }
    __syncthreads();
    float w0 = W[c*9+0], w1 = W[c*9+1], w2 = W[c*9+2];
    float w3 = W[c*9+3], w4 = W[c*9+4], w5 = W[c*9+5];
    float w6 = W[c*9+6], w7 = W[c*9+7], w8 = W[c*9+8];
    float bb = bias[c];
    float* dst = g_xc + ((long)b * 192 + c) * LQ;
    for (int e = tid; e < LQ; e += 256) {
        int h = e >> 6, w = e & 63;
        const float* r0 = sm + h * 68 + w;
        float acc = bb + r0[0]*w0 + r0[1]*w1 + r0[2]*w2
                       + r0[68]*w3 + r0[69]*w4 + r0[70]*w5
                       + r0[136]*w6 + r0[137]*w7 + r0[138]*w8;
        dst[e] = acc / (1.f + __expf(-acc));
    }
}

// ---------------- haar 1x1 conv + strided combine -> yL, y_mean ----------------
__global__ void haar_kernel(const float* __restrict__ Wh)
{
    extern __shared__ float smh[];
    float* sW = smh;
    float* s1 = smh + 32 * 192;
    float* s2 = s1 + 192 * 32;
    int i = blockIdx.x, b = blockIdx.y;
    int tid = threadIdx.x;
    for (int e = tid; e < 32 * 192; e += 256) sW[e] = Wh[e];
    const float* xcb = g_xc + (long)b * 192 * LQ;
    for (int e = tid; e < 192 * 32; e += 256) {
        int d = e >> 5, j = e & 31;
        const float* row0 = xcb + (long)d * LQ + (2 * i) * 64 + 2 * j;
        float xa = row0[0], xb = row0[1];
        float xc2 = row0[64], xd = row0[65];
        s1[d * 32 + j] = xa + xb + xc2 + xd;
        s2[d * 32 + j] = 3.f * xa - xb - xc2 - xd;
    }
    __syncthreads();
    for (int e = tid; e < 2048; e += 256) {
        int which = e >> 10;
        int ch = (e >> 5) & 31;
        int j = e & 31;
        const float* sv = (which ? s2 : s1) + j;
        const float* wr = sW + ch * 192;
        float acc = 0.f;
#pragma unroll 4
        for (int d = 0; d < 192; d++) acc += wr[d] * sv[d * 32];
        acc *= which ? (1.f / 6.f) : 0.5f;
        int n = ch >> 2;
        int lpos = (ch & 3) * 1024 + i * 32 + j;
        float* dst = which ? g_ym : g_yL;
        dst[((long)b * 8 + n) * LQ + lpos] = acc;
    }
}

// ---------------- fused: conv1d(k=7) + r-rows + B/C assembly ----------------
__global__ void convbc_kernel(const float* __restrict__ Wx, const float* __restrict__ bx)
{
    __shared__ float sIn[22][264];
    __shared__ float sWc[22 * 7];
    __shared__ float sbc[22];
    int tid = threadIdx.x;
    int l0 = blockIdx.x * 256;
    int b = blockIdx.y;

    for (int e = tid; e < 154; e += 256) sWc[e] = Wx[e];
    for (int e = tid; e < 22; e += 256) sbc[e] = bx[e];
    for (int e = tid; e < 22 * 262; e += 256) {
        int c = e / 262, p = e % 262;
        int l = l0 + p - 3;
        float v = 0.f;
        if ((unsigned)l < (unsigned)LQ) v = g_xdbl[((long)b * 22 + c) * LQ + l];
        sIn[c][p] = v;
    }
    __syncthreads();

    int l = l0 + tid;
    float r[22];
#pragma unroll
    for (int c = 0; c < 22; c++) {
        float acc = sbc[c];
#pragma unroll
        for (int k = 0; k < 7; k++) acc += sIn[c][tid + k] * sWc[c * 7 + k];
        r[c] = acc;
    }
    // write dt-rank rows for the scan's inline dt projection
    float* rout = g_rsm + (long)b * 6 * LQ + l;
#pragma unroll
    for (int rr = 0; rr < 6; rr++) rout[(long)rr * LQ] = r[rr];
    // B/C assembly
    float* o = g_BC + ((long)b * LQ + l) * 16;
    float bs[8], cs[8];
#pragma unroll
    for (int n = 0; n < 8; n++) {
        bs[n] = r[6 + n]  * g_yL[((long)b * 8 + n) * LQ + l] + 1e-6f;
        cs[n] = r[14 + n] * g_ym[((long)b * 8 + n) * LQ + l] + 1e-6f;
    }
    ((float4*)o)[0] = make_float4(bs[0], bs[1], bs[2], bs[3]);
    ((float4*)o)[1] = make_float4(bs[4], bs[5], bs[6], bs[7]);
    ((float4*)o)[2] = make_float4(cs[0], cs[1], cs[2], cs[3]);
    ((float4*)o)[3] = make_float4(cs[4], cs[5], cs[6], cs[7]);
}

// ---------------- selective scan (512 threads, 8 l/thread, inline dt-proj) ------------
// smem: only the Hillis-Steele buffer 2*8*512 floats = 32768 bytes.
#define SCAN_SMEM 32768

__device__ __forceinline__ void make_powers(float q, float* p)
{
    float q2 = q * q;
    float q4 = q2 * q2;
    p[0] = q;       p[1] = q2;      p[2] = q2 * q;  p[3] = q4;
    p[4] = q4 * q;  p[5] = q4 * q2; p[6] = p[5] * q; p[7] = q4 * q4;
}

__global__ void scan_kernel(const float* __restrict__ Ds,
                            const float* __restrict__ Wdt, const float* __restrict__ dtb)
{
    extern __shared__ float sScan[];   // [8][512] A | [8][512] B
    int bd = blockIdx.x;
    int b = bd / 192, d = bd % 192;
    int tid = threadIdx.x;             // 512
    int base = tid * 8;

    // u in registers
    const float* up = g_xc + ((long)b * 192 + d) * LQ;
    float u[8];
    *(float4*)&u[0] = *(const float4*)(up + base);
    *(float4*)&u[4] = *(const float4*)(up + base + 4);

    // inline dt projection + softplus -> delta registers
    float wdt[6];
#pragma unroll
    for (int rr = 0; rr < 6; rr++) wdt[rr] = Wdt[d * 6 + rr];
    float bdt = dtb[d];
    const float* rp = g_rsm + (long)b * 6 * LQ;
    float s8[8];
#pragma unroll
    for (int i = 0; i < 8; i++) s8[i] = bdt;
#pragma unroll
    for (int rr = 0; rr < 6; rr++) {
        float4 a = *(const float4*)(rp + (long)rr * LQ + base);
        float4 c = *(const float4*)(rp + (long)rr * LQ + base + 4);
        s8[0] += wdt[rr] * a.x; s8[1] += wdt[rr] * a.y;
        s8[2] += wdt[rr] * a.z; s8[3] += wdt[rr] * a.w;
        s8[4] += wdt[rr] * c.x; s8[5] += wdt[rr] * c.y;
        s8[6] += wdt[rr] * c.z; s8[7] += wdt[rr] * c.w;
    }
    float delta[8];
#pragma unroll
    for (int i = 0; i < 8; i++)
        delta[i] = (s8[i] > 20.f) ? s8[i] : log1pf(expf(s8[i]));

    float An[8];
#pragma unroll
    for (int n = 0; n < 8; n++) An[n] = g_A[d * 8 + n];
    bool powok = (g_pow_ok != 0);
    const float* bc = g_BC + (long)b * LQ * 16;

    // pass 1: per-thread chunk transform
    float a[8], hh[8];
#pragma unroll
    for (int n = 0; n < 8; n++) { a[n] = 1.f; hh[n] = 0.f; }
#pragma unroll
    for (int i = 0; i < 8; i++) {
        int l = base + i;
        float du = delta[i] * u[i];
        const float4* bc4 = (const float4*)(bc + (long)l * 16);
        float4 b0 = bc4[0], b1 = bc4[1];
        float bl[8] = {b0.x,b0.y,b0.z,b0.w,b1.x,b1.y,b1.z,b1.w};
        float p[8];
        if (powok) {
            make_powers(__expf(delta[i] * An[0]), p);
        } else {
#pragma unroll
            for (int n = 0; n < 8; n++) p[n] = __expf(delta[i] * An[n]);
        }
#pragma unroll
        for (int n = 0; n < 8; n++) {
            hh[n] = p[n] * hh[n] + du * bl[n];
            a[n] *= p[n];
        }
    }
#pragma unroll
    for (int n = 0; n < 8; n++) { sScan[n * 512 + tid] = a[n]; sScan[4096 + n * 512 + tid] = hh[n]; }
    __syncthreads();

    // inclusive Hillis-Steele over 512 chunk transforms
    for (int off = 1; off < 512; off <<= 1) {
        float pa[8], pb[8];
        if (tid >= off) {
#pragma unroll
            for (int n = 0; n < 8; n++) {
                pa[n] = sScan[n * 512 + tid - off];
                pb[n] = sScan[4096 + n * 512 + tid - off];
            }
        }
        __syncthreads();
        if (tid >= off) {
#pragma unroll
            for (int n = 0; n < 8; n++) {
                float a2 = sScan[n * 512 + tid];
                float b2 = sScan[4096 + n * 512 + tid];
                sScan[n * 512 + tid] = pa[n] * a2;
                sScan[4096 + n * 512 + tid] = a2 * pb[n] + b2;
            }
        }
        __syncthreads();
    }
    float h0[8];
#pragma unroll
    for (int n = 0; n < 8; n++) h0[n] = (tid == 0) ? 0.f : sScan[4096 + n * 512 + tid - 1];

    // pass 2: recompute with correct h_init, emit y directly (float4 stores)
    float Dd = Ds[d];
    float* yo = g_y + ((long)b * 192 + d) * LQ;
#pragma unroll
    for (int half = 0; half < 2; half++) {
        float yv[4];
#pragma unroll
        for (int q = 0; q < 4; q++) {
            int i = half * 4 + q;
            int l = base + i;
            float du = delta[i] * u[i];
            const float4* bc4 = (const float4*)(bc + (long)l * 16);
            float4 b0 = bc4[0], b1 = bc4[1], c0 = bc4[2], c1 = bc4[3];
            float bl[8] = {b0.x,b0.y,b0.z,b0.w,b1.x,b1.y,b1.z,b1.w};
            float cl[8] = {c0.x,c0.y,c0.z,c0.w,c1.x,c1.y,c1.z,c1.w};
            float p[8];
            if (powok) {
                make_powers(__expf(delta[i] * An[0]), p);
            } else {
#pragma unroll
                for (int n = 0; n < 8; n++) p[n] = __expf(delta[i] * An[n]);
            }
            float y = Dd * u[i];
#pragma unroll
            for (int n = 0; n < 8; n++) {
                h0[n] = p[n] * h0[n] + du * bl[n];
                y += h0[n] * cl[n];
            }
            yv[q] = y;
        }
        *(float4*)(yo + base + half * 4) = make_float4(yv[0], yv[1], yv[2], yv[3]);
    }
}

// ---------------- host launcher ----------------
extern "C" void kernel_launch(void* const* d_in, const int* in_sizes, int n_in,
                              void* d_out, int out_size)
{
    const float* x        = (const float*)d_in[0];
    const float* W_in     = (const float*)d_in[1];
    const float* W_dwc_i  = (const float*)d_in[2];
    const float* b_dwc_i  = (const float*)d_in[3];
    const float* W_dw3    = (const float*)d_in[4];
    const float* b_dw3    = (const float*)d_in[5];
    const float* W_dw5    = (const float*)d_in[6];
    const float* b_dw5    = (const float*)d_in[7];
    const float* W_dw7    = (const float*)d_in[8];
    const float* b_dw7    = (const float*)d_in[9];
    const float* W_dwc_f  = (const float*)d_in[10];
    const float* b_dwc_f  = (const float*)d_in[11];
    const float* W_conv2d = (const float*)d_in[12];
    const float* b_conv2d = (const float*)d_in[13];
    const float* W_haar   = (const float*)d_in[14];
    const float* x_proj_w = (const float*)d_in[15];
    const float* W_xconv  = (const float*)d_in[16];
    const float* b_xconv  = (const float*)d_in[17];
    const float* dt_w     = (const float*)d_in[18];
    const float* dt_b     = (const float*)d_in[19];
    const float* A_logs   = (const float*)d_in[20];
    const float* Ds       = (const float*)d_in[21];
    const float* ln_g     = (const float*)d_in[22];
    const float* ln_b     = (const float*)d_in[23];
    const float* W_out    = (const float*)d_in[24];
    float* out = (float*)d_out;

    float *p_xz, *p_t, *p_t2, *p_zsil, *p_xc, *p_xdbl, *p_y;
    cudaGetSymbolAddress((void**)&p_xz, g_xz);
    cudaGetSymbolAddress((void**)&p_t, g_t);
    cudaGetSymbolAddress((void**)&p_t2, g_t2);
    cudaGetSymbolAddress((void**)&p_zsil, g_zsil);
    cudaGetSymbolAddress((void**)&p_xc, g_xc);
    cudaGetSymbolAddress((void**)&p_xdbl, g_xdbl);
    cudaGetSymbolAddress((void**)&p_y, g_y);

    const int SMEM_SPLIT = (2*64*36 + 2*32*136) * 4;      // 53248
    const int SMEM_PIPE  = (2*WB_WORDS + 2*AB_WORDS) * 4; // 53248
    const int SMEM_LN    = SMEM_SPLIT + (128+128+192+192+256+256) * 4; // 57856
    cudaFuncSetAttribute((const void*)gemm_tf32_split_kernel,
                         cudaFuncAttributeMaxDynamicSharedMemorySize, SMEM_SPLIT);
    cudaFuncSetAttribute((const void*)gemm_tf32_pipe_kernel<1>,
                         cudaFuncAttributeMaxDynamicSharedMemorySize, SMEM_PIPE);
    cudaFuncSetAttribute((const void*)gemm_tf32_pipe_kernel<2>,
                         cudaFuncAttributeMaxDynamicSharedMemorySize, SMEM_PIPE);
    cudaFuncSetAttribute((const void*)gemm_ln_kernel,
                         cudaFuncAttributeMaxDynamicSharedMemorySize, SMEM_LN);
    cudaFuncSetAttribute(haar_kernel, cudaFuncAttributeMaxDynamicSharedMemorySize, 73728);
    cudaFuncSetAttribute(scan_kernel, cudaFuncAttributeMaxDynamicSharedMemorySize, SCAN_SMEM);

    static cudaStream_t sZ = nullptr;
    static cudaEvent_t evFork = nullptr, evJoin = nullptr;
    if (!sZ) {
        cudaStreamCreateWithFlags(&sZ, cudaStreamNonBlocking);
        cudaEventCreateWithFlags(&evFork, cudaEventDisableTiming);
        cudaEventCreateWithFlags(&evJoin, cudaEventDisableTiming);
    }

    prep_kernel<<<1, 256>>>(A_logs);

    // K1: input GEMM (split tf32, ~fp32 accuracy)
    gemm_tf32_split_kernel<<<dim3(32, 6, NB), 256, SMEM_SPLIT>>>(
        x, 96L * LQ, W_in, nullptr, p_xz, 384L * LQ, 384, 96);

    // ---- fork: z branch on stream sZ ----
    cudaEventRecord(evFork, 0);
    cudaStreamWaitEvent(sZ, evFork, 0);

    gemm_tf32_pipe_kernel<1><<<dim3(32, 6, NB), 256, SMEM_PIPE, sZ>>>(
        p_xz + 192L * LQ, 384L * LQ, W_dwc_i, b_dwc_i, p_t, p_t2, 384L * LQ, 384, 192);
    dwconv_all_kernel<<<dim3(288, NB), 256, 0, sZ>>>(W_dw3, b_dw3, W_dw5, b_dw5, W_dw7, b_dw7);
    gemm_tf32_pipe_kernel<2><<<dim3(32, 3, NB), 256, SMEM_PIPE, sZ>>>(
        p_t2, 384L * LQ, W_dwc_f, b_dwc_f, p_zsil, nullptr, 192L * LQ, 192, 384);
    cudaEventRecord(evJoin, sZ);

    // ---- x branch on default stream ----
    dw3_silu_kernel<<<dim3(192, NB), 256>>>(W_conv2d, b_conv2d);
    haar_kernel<<<dim3(32, NB), 256, 73728>>>(W_haar);
    gemm_tf32_split_kernel<<<dim3(32, 1, NB), 256, SMEM_SPLIT>>>(
        p_xc, 192L * LQ, x_proj_w, nullptr, p_xdbl, 22L * LQ, 22, 192);
    convbc_kernel<<<dim3(16, NB), 256>>>(W_xconv, b_xconv);
    scan_kernel<<<NB * 192, 512, SCAN_SMEM>>>(Ds, dt_w, dt_b);

    // ---- join, then fused LN+gate+output GEMM ----
    cudaStreamWaitEvent(0, evJoin, 0);
    gemm_ln_kernel<<<dim3(32, 2, NB), 256, SMEM_LN>>>(
        p_y, p_zsil, ln_g, ln_b, W_out, out, 96, 192);
    (void)in_sizes; (void)n_in; (void)out_size;
}